// round 15
// baseline (speedup 1.0000x reference)
#include <cuda_runtime.h>
#include <cuda_bf16.h>
#include <math.h>
#include <stdint.h>

#define WIN   512
#define BATCH 8
#define CIN   38
#define COUT  38
#define DM    512
#define NH    8
#define EHD   64
#define NL    3
#define ROWS  (BATCH*WIN)   /* 4096 */

#define OUT_ELEMS    (BATCH*WIN*COUT)
#define LAYER_ELEMS  ((size_t)BATCH*NH*WIN*WIN)
#define SERIES_OFF   ((size_t)OUT_ELEMS)
#define PRIOR_OFF    (SERIES_OFF + 3*LAYER_ELEMS)
#define SIGMA_OFF    (PRIOR_OFF  + 3*LAYER_ELEMS)

// ---------------- scratch ---------------------------------------------------
__device__ float g_h [ROWS*DM];
__device__ float g_t2[ROWS*DM];
__device__ float g_sig[ROWS*NH];
__device__ __nv_bfloat16 g_hh [ROWS*DM];
__device__ __nv_bfloat16 g_hl [ROWS*DM];
__device__ __nv_bfloat16 g_qh [ROWS*DM];
__device__ __nv_bfloat16 g_ql [ROWS*DM];
__device__ __nv_bfloat16 g_kh [ROWS*DM];
__device__ __nv_bfloat16 g_kl [ROWS*DM];
__device__ __nv_bfloat16 g_vh [ROWS*DM];
__device__ __nv_bfloat16 g_vl [ROWS*DM];
__device__ __nv_bfloat16 g_t1h[ROWS*DM];
__device__ __nv_bfloat16 g_t1l[ROWS*DM];
__device__ __nv_bfloat16 g_wh [18*262144];   // TRANSPOSED [N,K] hi planes
__device__ __nv_bfloat16 g_wl [18*262144];   // TRANSPOSED [N,K] lo planes

// ---------------- helpers ---------------------------------------------------
__device__ __forceinline__ uint32_t smaddr(const void* p) {
    return (uint32_t)__cvta_generic_to_shared(p);
}
__device__ __forceinline__ void ldsm4(uint32_t a, uint32_t& r0, uint32_t& r1,
                                      uint32_t& r2, uint32_t& r3) {
    asm volatile("ldmatrix.sync.aligned.m8n8.x4.shared.b16 {%0,%1,%2,%3}, [%4];\n"
                 : "=r"(r0), "=r"(r1), "=r"(r2), "=r"(r3) : "r"(a));
}
__device__ __forceinline__ void ldsm2t(uint32_t a, uint32_t& r0, uint32_t& r1) {
    asm volatile("ldmatrix.sync.aligned.m8n8.x2.trans.shared.b16 {%0,%1}, [%2];\n"
                 : "=r"(r0), "=r"(r1) : "r"(a));
}
__device__ __forceinline__ void mmabf(float* d, const uint32_t* a, uint32_t b0, uint32_t b1) {
    asm volatile("mma.sync.aligned.m16n8k16.row.col.f32.bf16.bf16.f32 "
                 "{%0,%1,%2,%3}, {%4,%5,%6,%7}, {%8,%9}, {%0,%1,%2,%3};\n"
                 : "+f"(d[0]), "+f"(d[1]), "+f"(d[2]), "+f"(d[3])
                 : "r"(a[0]), "r"(a[1]), "r"(a[2]), "r"(a[3]), "r"(b0), "r"(b1));
}
__device__ __forceinline__ void cvst(float x, float y, __nv_bfloat16* ph, __nv_bfloat16* pl) {
    __nv_bfloat16 h0 = __float2bfloat16_rn(x);
    __nv_bfloat16 l0 = __float2bfloat16_rn(x - __bfloat162float(h0));
    __nv_bfloat16 h1 = __float2bfloat16_rn(y);
    __nv_bfloat16 l1 = __float2bfloat16_rn(y - __bfloat162float(h1));
    *(__nv_bfloat162*)ph = __halves2bfloat162(h0, h1);
    *(__nv_bfloat162*)pl = __halves2bfloat162(l0, l1);
}
__device__ __forceinline__ void cvst1(float x, __nv_bfloat16* ph, __nv_bfloat16* pl) {
    __nv_bfloat16 h0 = __float2bfloat16_rn(x);
    *ph = h0;
    *pl = __float2bfloat16_rn(x - __bfloat162float(h0));
}
__device__ __forceinline__ void cpa16(uint32_t s, const void* g) {
    asm volatile("cp.async.ca.shared.global [%0], [%1], 16;\n" :: "r"(s), "l"(g));
}

// ---------------- weight pre-conversion: transpose to [N,K] + split ---------
__global__ __launch_bounds__(256)
void wconv_kernel(const float* __restrict__ Wq, const float* __restrict__ Wk,
                  const float* __restrict__ Wv, const float* __restrict__ Wo,
                  const float* __restrict__ W1, const float* __restrict__ W2,
                  __nv_bfloat16* __restrict__ wh, __nv_bfloat16* __restrict__ wl) {
    __shared__ float tile[64][65];
    int m = blockIdx.y;               // 0..17
    int u = m % 6, i = m / 6;
    const float* src;
    switch (u) { case 0: src=Wq; break; case 1: src=Wk; break; case 2: src=Wv; break;
                 case 3: src=Wo; break; case 4: src=W1; break; default: src=W2; }
    src += (size_t)i * 262144;
    int t = blockIdx.x;               // 0..63
    int k0 = (t >> 3) * 64, n0 = (t & 7) * 64;
    int tid = threadIdx.x;
    for (int idx = tid; idx < 4096; idx += 256) {
        int r = idx >> 6, c = idx & 63;
        tile[r][c] = src[(size_t)(k0 + r)*512 + n0 + c];   // tile[k][n]
    }
    __syncthreads();
    __nv_bfloat16* dh = wh + (size_t)m * 262144;
    __nv_bfloat16* dl = wl + (size_t)m * 262144;
    for (int idx = tid; idx < 4096; idx += 256) {
        int r = idx >> 6, c = idx & 63;     // r = n-local, c = k-local
        cvst1(tile[c][r], dh + (size_t)(n0 + r)*512 + k0 + c,
                          dl + (size_t)(n0 + r)*512 + k0 + c);
    }
}

// ---------------- embedding -------------------------------------------------
__global__ void embed_kernel(const float* __restrict__ x,
                             const float* __restrict__ ck,
                             float* __restrict__ h,
                             __nv_bfloat16* __restrict__ hh,
                             __nv_bfloat16* __restrict__ hl) {
    int bt = blockIdx.x;
    int b = bt >> 9, t = bt & (WIN-1);
    __shared__ float xs[3*CIN];
    int tid = threadIdx.x;
    if (tid < 3*CIN) {
        int w = tid / CIN, c = tid % CIN;
        int src = (t + w - 1 + WIN) & (WIN-1);
        xs[tid] = x[((size_t)b*WIN + src)*CIN + c];
    }
    __syncthreads();
    int d = tid;
    int i2 = (d >> 1) * 2;
    float ang = (float)t * __expf(-(float)i2 * (9.210340371976184f/512.0f));
    float acc = (d & 1) ? cosf(ang) : sinf(ang);
#pragma unroll 1
    for (int wc = 0; wc < 3*CIN; wc++)
        acc += xs[wc] * ck[(size_t)wc*DM + d];
    size_t idx = (size_t)bt*DM + d;
    h[idx] = acc;
    cvst1(acc, hh + idx, hl + idx);
}

// ---------------- dense GEMM: 64x128, [N,K] weights, no trans ldsm ----------
struct GemmJob {
    const __nv_bfloat16* Wh; const __nv_bfloat16* Wl;   // transposed [N,K]
    const float* bias;
    float* Cf; __nv_bfloat16* Ch; __nv_bfloat16* Cl;
};

#define AH_OFF 0
#define AL_OFF 2560
#define BH_OFF 5120
#define BL_OFF 10240
#define BUF_SZ 15360   /* halves per buffer */
#define MG_SMEM (2*BUF_SZ*2)   /* 61440 B */

__device__ __forceinline__ void mg_issue(uint32_t smb, int buf, int tid,
        const __nv_bfloat16* Ah, const __nv_bfloat16* Al,
        const __nv_bfloat16* Wh, const __nv_bfloat16* Wl, int kt) {
    uint32_t base = smb + (uint32_t)buf * (BUF_SZ*2);
    // A: 64 rows x 32 k-halves, stride 40
    int ar = tid >> 2, ac = (tid & 3) * 8;
    const __nv_bfloat16* ga  = Ah + (size_t)ar*512 + kt*32 + ac;
    const __nv_bfloat16* gal = Al + (size_t)ar*512 + kt*32 + ac;
    cpa16(base + (uint32_t)(AH_OFF + ar*40 + ac)*2, ga);
    cpa16(base + (uint32_t)(AL_OFF + ar*40 + ac)*2, gal);
    // B ([N,K]): 128 n-rows x 32 k-halves, stride 40
    int br = tid >> 1, bc = (tid & 1) * 16;
    const __nv_bfloat16* gb  = Wh + (size_t)br*512 + kt*32 + bc;
    const __nv_bfloat16* gbl = Wl + (size_t)br*512 + kt*32 + bc;
    uint32_t sb  = base + (uint32_t)(BH_OFF + br*40 + bc)*2;
    uint32_t sbl = base + (uint32_t)(BL_OFF + br*40 + bc)*2;
    cpa16(sb, gb);        cpa16(sb+16, gb+8);
    cpa16(sbl, gbl);      cpa16(sbl+16, gbl+8);
    asm volatile("cp.async.commit_group;\n");
}

__device__ __forceinline__ void mg_compute(uint32_t smb, int buf, int tid,
                                           float (*acc)[4][4]) {
    int l = tid & 31, w = tid >> 5, wm = w & 1, wn = w >> 1;
    int lr = l & 15, lc8 = (l >> 4) << 3;
    uint32_t base = smb + (uint32_t)buf * (BUF_SZ*2);
#pragma unroll
    for (int ks = 0; ks < 32; ks += 16) {
        uint32_t ah[2][4], al[2][4];
#pragma unroll
        for (int fm = 0; fm < 2; fm++) {
            uint32_t aoff = (uint32_t)((wm*32 + fm*16 + lr)*40 + ks + lc8) * 2;
            ldsm4(base + AH_OFF*2 + aoff, ah[fm][0], ah[fm][1], ah[fm][2], ah[fm][3]);
            ldsm4(base + AL_OFF*2 + aoff, al[fm][0], al[fm][1], al[fm][2], al[fm][3]);
        }
#pragma unroll
        for (int fnp = 0; fnp < 2; fnp++) {
            // non-trans B: n-major rows, K-contiguous (same pattern as scores K)
            uint32_t boff = (uint32_t)((wn*32 + fnp*16 + lr)*40 + ks + lc8) * 2;
            uint32_t bh[4], bl[4];
            ldsm4(base + BH_OFF*2 + boff, bh[0], bh[1], bh[2], bh[3]);
            ldsm4(base + BL_OFF*2 + boff, bl[0], bl[1], bl[2], bl[3]);
#pragma unroll
            for (int fm = 0; fm < 2; fm++) {
                mmabf(acc[fm][fnp*2],   ah[fm], bh[0], bh[2]);
                mmabf(acc[fm][fnp*2],   ah[fm], bl[0], bl[2]);
                mmabf(acc[fm][fnp*2],   al[fm], bh[0], bh[2]);
                mmabf(acc[fm][fnp*2+1], ah[fm], bh[1], bh[3]);
                mmabf(acc[fm][fnp*2+1], ah[fm], bl[1], bl[3]);
                mmabf(acc[fm][fnp*2+1], al[fm], bh[1], bh[3]);
            }
        }
    }
}

template<bool GELU>
__global__ __launch_bounds__(256, 3)
void mgemm(const __nv_bfloat16* __restrict__ Ah, const __nv_bfloat16* __restrict__ Al,
           GemmJob j0, GemmJob j1, GemmJob j2) {
    extern __shared__ __nv_bfloat16 sm[];
    GemmJob jb = (blockIdx.z == 0) ? j0 : ((blockIdx.z == 1) ? j1 : j2);
    int tid = threadIdx.x;
    const __nv_bfloat16* Abh = Ah + (size_t)blockIdx.x * 64 * 512;
    const __nv_bfloat16* Abl = Al + (size_t)blockIdx.x * 64 * 512;
    const __nv_bfloat16* Wbh = jb.Wh + (size_t)blockIdx.y * 128 * 512;  // [N,K]
    const __nv_bfloat16* Wbl = jb.Wl + (size_t)blockIdx.y * 128 * 512;
    uint32_t smb = smaddr(sm);

    mg_issue(smb, 0, tid, Abh, Abl, Wbh, Wbl, 0);
    mg_issue(smb, 1, tid, Abh, Abl, Wbh, Wbl, 1);

    float acc[2][4][4] = {};
    for (int kt = 0; kt < 16; kt++) {
        int buf = kt & 1;
        if (kt < 15) asm volatile("cp.async.wait_group 1;\n");
        else         asm volatile("cp.async.wait_group 0;\n");
        __syncthreads();
        mg_compute(smb, buf, tid, acc);
        if (kt < 14) {
            __syncthreads();
            mg_issue(smb, buf, tid, Abh, Abl, Wbh, Wbl, kt+2);
        }
    }

    int l = tid & 31, w = tid >> 5, wm = w & 1, wn = w >> 1;
    int g = l >> 2, t2 = (l & 3) * 2;
    int rowb = blockIdx.x*64 + wm*32;
    int colb = blockIdx.y*128 + wn*32;
#pragma unroll
    for (int fm = 0; fm < 2; fm++) {
#pragma unroll
        for (int fn = 0; fn < 4; fn++) {
            int col = colb + fn*8 + t2;
            float bx0 = jb.bias[col], bx1 = jb.bias[col+1];
            float o0 = acc[fm][fn][0] + bx0, o1 = acc[fm][fn][1] + bx1;
            float o2 = acc[fm][fn][2] + bx0, o3 = acc[fm][fn][3] + bx1;
            if (GELU) {
                o0 = 0.5f*o0*(1.0f + erff(o0*0.70710678118654752f));
                o1 = 0.5f*o1*(1.0f + erff(o1*0.70710678118654752f));
                o2 = 0.5f*o2*(1.0f + erff(o2*0.70710678118654752f));
                o3 = 0.5f*o3*(1.0f + erff(o3*0.70710678118654752f));
            }
            int r0 = rowb + fm*16 + g;
            if (jb.Cf) {
                float2 p0 = {o0, o1}, p1 = {o2, o3};
                *(float2*)(jb.Cf + (size_t)r0*512 + col)     = p0;
                *(float2*)(jb.Cf + (size_t)(r0+8)*512 + col) = p1;
            }
            if (jb.Ch) {
                cvst(o0, o1, jb.Ch + (size_t)r0*512 + col,     jb.Cl + (size_t)r0*512 + col);
                cvst(o2, o3, jb.Ch + (size_t)(r0+8)*512 + col, jb.Cl + (size_t)(r0+8)*512 + col);
            }
        }
    }
}

// ---------------- fused scores + softmax + S@V ------------------------------
#define FQH 0
#define FQL 4608
#define FKH 9216
#define FKL 46080
#define FVH 0
#define FVL 4608
#define FSH 9216
#define FSL 42496
#define FS_SMEM 165888

__global__ __launch_bounds__(512)
void fscores(const __nv_bfloat16* __restrict__ qh, const __nv_bfloat16* __restrict__ ql,
             const __nv_bfloat16* __restrict__ kh, const __nv_bfloat16* __restrict__ kl,
             const __nv_bfloat16* __restrict__ vh, const __nv_bfloat16* __restrict__ vl,
             float* __restrict__ out,
             __nv_bfloat16* __restrict__ t1h, __nv_bfloat16* __restrict__ t1l) {
    extern __shared__ __nv_bfloat16 sm[];
    __shared__ float red[64][8];
    int tid = threadIdx.x;
    int bh = blockIdx.y, b = bh >> 3, hhd = bh & 7;
    int l0 = blockIdx.x * 64;

    {
        int r = tid >> 3, c = (tid & 7) * 8;
        size_t qoff = ((size_t)(b*512 + l0 + r))*512 + hhd*64 + c;
        int qi = r*72 + c;
        *(uint4*)&sm[FQH + qi] = *(const uint4*)(qh + qoff);
        *(uint4*)&sm[FQL + qi] = *(const uint4*)(ql + qoff);
#pragma unroll
        for (int i = 0; i < 8; i++) {
            int kr = r + i*64;
            size_t koff = ((size_t)(b*512 + kr))*512 + hhd*64 + c;
            int ki = kr*72 + c;
            *(uint4*)&sm[FKH + ki] = *(const uint4*)(kh + koff);
            *(uint4*)&sm[FKL + ki] = *(const uint4*)(kl + koff);
        }
    }
    __syncthreads();

    uint32_t smb = smaddr(sm);
    int l = tid & 31, w = tid >> 5;
    int wn = w & 7, wm = w >> 3;
    int lr = l & 15, lc8 = (l >> 4) << 3;
    float acc[2][8][4] = {};
#pragma unroll
    for (int ks = 0; ks < 64; ks += 16) {
        uint32_t ah[2][4], al[2][4];
#pragma unroll
        for (int fm = 0; fm < 2; fm++) {
            uint32_t aoff = (uint32_t)((wm*32 + fm*16 + lr)*72 + ks + lc8) * 2;
            ldsm4(smb + FQH*2 + aoff, ah[fm][0], ah[fm][1], ah[fm][2], ah[fm][3]);
            ldsm4(smb + FQL*2 + aoff, al[fm][0], al[fm][1], al[fm][2], al[fm][3]);
        }
#pragma unroll
        for (int fnp = 0; fnp < 4; fnp++) {
            uint32_t boff = (uint32_t)((wn*64 + fnp*16 + lr)*72 + ks + lc8) * 2;
            uint32_t khr[4], klr[4];
            ldsm4(smb + FKH*2 + boff, khr[0], khr[1], khr[2], khr[3]);
            ldsm4(smb + FKL*2 + boff, klr[0], klr[1], klr[2], klr[3]);
#pragma unroll
            for (int fm = 0; fm < 2; fm++) {
                mmabf(acc[fm][fnp*2],   ah[fm], khr[0], khr[2]);
                mmabf(acc[fm][fnp*2],   ah[fm], klr[0], klr[2]);
                mmabf(acc[fm][fnp*2],   al[fm], khr[0], khr[2]);
                mmabf(acc[fm][fnp*2+1], ah[fm], khr[1], khr[3]);
                mmabf(acc[fm][fnp*2+1], ah[fm], klr[1], klr[3]);
                mmabf(acc[fm][fnp*2+1], al[fm], khr[1], khr[3]);
            }
        }
    }

#pragma unroll
    for (int fm = 0; fm < 2; fm++)
#pragma unroll
        for (int fn = 0; fn < 8; fn++)
#pragma unroll
            for (int e = 0; e < 4; e++) acc[fm][fn][e] *= 0.125f;

    int g = l >> 2, t2 = (l & 3) * 2;
    float tmax[2][2] = {{-1e30f,-1e30f},{-1e30f,-1e30f}};
#pragma unroll
    for (int fm = 0; fm < 2; fm++)
#pragma unroll
        for (int fn = 0; fn < 8; fn++) {
            tmax[fm][0] = fmaxf(tmax[fm][0], fmaxf(acc[fm][fn][0], acc[fm][fn][1]));
            tmax[fm][1] = fmaxf(tmax[fm][1], fmaxf(acc[fm][fn][2], acc[fm][fn][3]));
        }
#pragma unroll
    for (int o = 1; o <= 2; o <<= 1) {
#pragma unroll
        for (int fm = 0; fm < 2; fm++) {
            tmax[fm][0] = fmaxf(tmax[fm][0], __shfl_xor_sync(0xffffffff, tmax[fm][0], o));
            tmax[fm][1] = fmaxf(tmax[fm][1], __shfl_xor_sync(0xffffffff, tmax[fm][1], o));
        }
    }
    if ((l & 3) == 0) {
#pragma unroll
        for (int fm = 0; fm < 2; fm++) {
            red[wm*32 + fm*16 + g][wn]     = tmax[fm][0];
            red[wm*32 + fm*16 + g + 8][wn] = tmax[fm][1];
        }
    }
    __syncthreads();
    float rmax[2][2];
#pragma unroll
    for (int fm = 0; fm < 2; fm++)
#pragma unroll
        for (int hf = 0; hf < 2; hf++) {
            int r = wm*32 + fm*16 + g + hf*8;
            float m = red[r][0];
#pragma unroll
            for (int ww = 1; ww < 8; ww++) m = fmaxf(m, red[r][ww]);
            rmax[fm][hf] = m;
        }
    __syncthreads();

    float tsum[2][2] = {};
#pragma unroll
    for (int fm = 0; fm < 2; fm++)
#pragma unroll
        for (int fn = 0; fn < 8; fn++) {
            acc[fm][fn][0] = __expf(acc[fm][fn][0] - rmax[fm][0]);
            acc[fm][fn][1] = __expf(acc[fm][fn][1] - rmax[fm][0]);
            acc[fm][fn][2] = __expf(acc[fm][fn][2] - rmax[fm][1]);
            acc[fm][fn][3] = __expf(acc[fm][fn][3] - rmax[fm][1]);
            tsum[fm][0] += acc[fm][fn][0] + acc[fm][fn][1];
            tsum[fm][1] += acc[fm][fn][2] + acc[fm][fn][3];
        }
#pragma unroll
    for (int o = 1; o <= 2; o <<= 1) {
#pragma unroll
        for (int fm = 0; fm < 2; fm++) {
            tsum[fm][0] += __shfl_xor_sync(0xffffffff, tsum[fm][0], o);
            tsum[fm][1] += __shfl_xor_sync(0xffffffff, tsum[fm][1], o);
        }
    }
    if ((l & 3) == 0) {
#pragma unroll
        for (int fm = 0; fm < 2; fm++) {
            red[wm*32 + fm*16 + g][wn]     = tsum[fm][0];
            red[wm*32 + fm*16 + g + 8][wn] = tsum[fm][1];
        }
    }
    __syncthreads();
    float rinv[2][2];
#pragma unroll
    for (int fm = 0; fm < 2; fm++)
#pragma unroll
        for (int hf = 0; hf < 2; hf++) {
            int r = wm*32 + fm*16 + g + hf*8;
            float s = red[r][0];
#pragma unroll
            for (int ww = 1; ww < 8; ww++) s += red[r][ww];
            rinv[fm][hf] = 1.0f / s;
        }

    float* ob = out + ((size_t)bh*512 + l0)*512;
#pragma unroll
    for (int fm = 0; fm < 2; fm++)
#pragma unroll
        for (int fn = 0; fn < 8; fn++) {
            int row0 = wm*32 + fm*16 + g;
            int col = wn*64 + fn*8 + t2;
            float s0 = acc[fm][fn][0]*rinv[fm][0], s1 = acc[fm][fn][1]*rinv[fm][0];
            float s2 = acc[fm][fn][2]*rinv[fm][1], s3 = acc[fm][fn][3]*rinv[fm][1];
            float2 p0 = {s0, s1}, p1 = {s2, s3};
            *(float2*)(ob + (size_t)row0*512 + col)     = p0;
            *(float2*)(ob + (size_t)(row0+8)*512 + col) = p1;
            cvst(s0, s1, &sm[FSH + row0*520 + col],     &sm[FSL + row0*520 + col]);
            cvst(s2, s3, &sm[FSH + (row0+8)*520 + col], &sm[FSL + (row0+8)*520 + col]);
        }
    __syncthreads();

    float acc2[2][4] = {};
    for (int kc = 0; kc < 8; kc++) {
        {
            int r = tid >> 3, c = (tid & 7) * 8;
            size_t voff = ((size_t)(b*512 + kc*64 + r))*512 + hhd*64 + c;
            *(uint4*)&sm[FVH + r*72 + c] = *(const uint4*)(vh + voff);
            *(uint4*)&sm[FVL + r*72 + c] = *(const uint4*)(vl + voff);
        }
        __syncthreads();
#pragma unroll
        for (int ks = 0; ks < 64; ks += 16) {
            uint32_t sa[2][4], sl2[2][4];
#pragma unroll
            for (int fm = 0; fm < 2; fm++) {
                uint32_t aoff = (uint32_t)((wm*32 + fm*16 + lr)*520 + kc*64 + ks + lc8) * 2;
                ldsm4(smb + FSH*2 + aoff, sa[fm][0], sa[fm][1], sa[fm][2], sa[fm][3]);
                ldsm4(smb + FSL*2 + aoff, sl2[fm][0], sl2[fm][1], sl2[fm][2], sl2[fm][3]);
            }
            uint32_t boff = (uint32_t)((ks + lr)*72 + wn*8) * 2;
            uint32_t bh2[2], bl2[2];
            ldsm2t(smb + FVH*2 + boff, bh2[0], bh2[1]);
            ldsm2t(smb + FVL*2 + boff, bl2[0], bl2[1]);
#pragma unroll
            for (int fm = 0; fm < 2; fm++) {
                mmabf(acc2[fm], sa[fm],  bh2[0], bh2[1]);
                mmabf(acc2[fm], sa[fm],  bl2[0], bl2[1]);
                mmabf(acc2[fm], sl2[fm], bh2[0], bh2[1]);
            }
        }
        if (kc < 7) __syncthreads();
    }

#pragma unroll
    for (int fm = 0; fm < 2; fm++) {
        int row0 = wm*32 + fm*16 + g;
        int col = wn*8 + t2;
        size_t p0 = ((size_t)(b*512 + l0 + row0))*512 + hhd*64 + col;
        size_t p1 = ((size_t)(b*512 + l0 + row0 + 8))*512 + hhd*64 + col;
        cvst(acc2[fm][0], acc2[fm][1], t1h + p0, t1l + p0);
        cvst(acc2[fm][2], acc2[fm][3], t1h + p1, t1l + p1);
    }
}

// ---------------- sigma projection ------------------------------------------
__global__ __launch_bounds__(128)
void sig4_kernel(const float* __restrict__ h, const float* __restrict__ Ws,
                 const float* __restrict__ bs, float* __restrict__ sig) {
    int warp = threadIdx.x >> 5, lane = threadIdx.x & 31;
    int row = blockIdx.x*4 + warp;
    const float* hr = h + (size_t)row*512;
    float s[8] = {};
#pragma unroll
    for (int i = 0; i < 16; i++) {
        int k = i*32 + lane;
        float hv = hr[k];
        float4 wa = *(const float4*)(Ws + k*8);
        float4 wb = *(const float4*)(Ws + k*8 + 4);
        s[0] += hv*wa.x; s[1] += hv*wa.y; s[2] += hv*wa.z; s[3] += hv*wa.w;
        s[4] += hv*wb.x; s[5] += hv*wb.y; s[6] += hv*wb.z; s[7] += hv*wb.w;
    }
#pragma unroll
    for (int off = 16; off > 0; off >>= 1)
#pragma unroll
        for (int o = 0; o < 8; o++) s[o] += __shfl_xor_sync(0xffffffff, s[o], off);
    if (lane < 8) sig[row*8 + lane] = s[lane] + bs[lane];
}

// ---------------- prior + sigma ---------------------------------------------
__global__ __launch_bounds__(128)
void prior_kernel(const float* __restrict__ sig,
                  float* __restrict__ prior, float* __restrict__ sigma) {
    int idx = blockIdx.x;
    int l = idx & (WIN-1);
    int bh = idx >> 9;
    int b = bh >> 3, hh = bh & 7;
    float sv = sig[((size_t)b*WIN + l)*NH + hh];
    float sgm = 1.0f/(1.0f + __expf(-5.0f*sv)) + 1e-5f;
    float sg  = __expf(sgm * 1.0986122886681098f) - 1.0f;
    float inv = 0.3989422804014327f / sg;
    float cc  = -1.0f/(2.0f*sg*sg);
    size_t base = ((size_t)bh*WIN + l)*WIN;
    int s0 = threadIdx.x * 4;
    float d0 = (float)(l - s0), d1 = d0 - 1.0f, d2 = d0 - 2.0f, d3 = d0 - 3.0f;
    float4 pr;
    pr.x = inv*__expf(cc*d0*d0); pr.y = inv*__expf(cc*d1*d1);
    pr.z = inv*__expf(cc*d2*d2); pr.w = inv*__expf(cc*d3*d3);
    *(float4*)(prior + base + s0) = pr;
    float4 sgv = {sg, sg, sg, sg};
    *(float4*)(sigma + base + s0) = sgv;
}

// ---------------- LayerNorm -------------------------------------------------
__global__ void ln_kernel(const float* __restrict__ x, const float* __restrict__ res,
                          const float* __restrict__ g, const float* __restrict__ bb,
                          float* __restrict__ outf,
                          __nv_bfloat16* __restrict__ outh, __nv_bfloat16* __restrict__ outl) {
    size_t row = blockIdx.x;
    int tid = threadIdx.x;
    const float* xr = x + row*DM;
    float v0 = xr[tid], v1 = xr[tid+256];
    if (res) { const float* rr = res + row*DM; v0 += rr[tid]; v1 += rr[tid+256]; }
    __shared__ float red[256];
    red[tid] = v0 + v1;
    __syncthreads();
    for (int s = 128; s > 0; s >>= 1) { if (tid < s) red[tid] += red[tid+s]; __syncthreads(); }
    float mu = red[0] * (1.0f/DM);
    __syncthreads();
    float d0 = v0 - mu, d1 = v1 - mu;
    red[tid] = d0*d0 + d1*d1;
    __syncthreads();
    for (int s = 128; s > 0; s >>= 1) { if (tid < s) red[tid] += red[tid+s]; __syncthreads(); }
    float r = rsqrtf(red[0]*(1.0f/DM) + 1e-3f);
    float y0 = d0*r*g[tid]     + bb[tid];
    float y1 = d1*r*g[tid+256] + bb[tid+256];
    size_t i0 = row*DM + tid, i1 = i0 + 256;
    outf[i0] = y0;
    outf[i1] = y1;
    if (outh) {
        cvst1(y0, outh + i0, outl + i0);
        cvst1(y1, outh + i1, outl + i1);
    }
}

// ---------------- fused final LayerNorm + projection -------------------------
__global__ void lnproj_kernel(const float* __restrict__ x,
                              const float* __restrict__ g, const float* __restrict__ bb,
                              const float* __restrict__ Wp, const float* __restrict__ bp,
                              float* __restrict__ out) {
    __shared__ float hs[512];
    __shared__ float red[256];
    size_t row = blockIdx.x;
    int tid = threadIdx.x;
    const float* xr = x + row*DM;
    float v0 = xr[tid], v1 = xr[tid+256];
    red[tid] = v0 + v1;
    __syncthreads();
    for (int s = 128; s > 0; s >>= 1) { if (tid < s) red[tid] += red[tid+s]; __syncthreads(); }
    float mu = red[0] * (1.0f/DM);
    __syncthreads();
    float d0 = v0 - mu, d1 = v1 - mu;
    red[tid] = d0*d0 + d1*d1;
    __syncthreads();
    for (int s = 128; s > 0; s >>= 1) { if (tid < s) red[tid] += red[tid+s]; __syncthreads(); }
    float r = rsqrtf(red[0]*(1.0f/DM) + 1e-3f);
    hs[tid]     = d0*r*g[tid]     + bb[tid];
    hs[tid+256] = d1*r*g[tid+256] + bb[tid+256];
    __syncthreads();
    int warp = tid >> 5, lane = tid & 31;
    for (int c = warp; c < COUT; c += 8) {
        float sum = 0.f;
#pragma unroll
        for (int k2 = lane; k2 < 512; k2 += 32) sum += hs[k2] * Wp[(size_t)k2*COUT + c];
#pragma unroll
        for (int o = 16; o > 0; o >>= 1) sum += __shfl_xor_sync(0xffffffff, sum, o);
        if (lane == 0) out[row*COUT + c] = sum + bp[c];
    }
}

// ---------------- host orchestration ----------------------------------------
extern "C" void kernel_launch(void* const* d_in, const int* in_sizes, int n_in,
                              void* d_out, int out_size) {
    const float* x    = (const float*)d_in[0];
    const float* ck   = (const float*)d_in[1];
    const float* Wq   = (const float*)d_in[2];
    const float* bq   = (const float*)d_in[3];
    const float* Wk   = (const float*)d_in[4];
    const float* bk   = (const float*)d_in[5];
    const float* Wv   = (const float*)d_in[6];
    const float* bv   = (const float*)d_in[7];
    const float* Ws   = (const float*)d_in[8];
    const float* bs   = (const float*)d_in[9];
    const float* Wo   = (const float*)d_in[10];
    const float* bo   = (const float*)d_in[11];
    const float* W1   = (const float*)d_in[12];
    const float* b1   = (const float*)d_in[13];
    const float* W2   = (const float*)d_in[14];
    const float* b2   = (const float*)d_in[15];
    const float* ln1g = (const float*)d_in[16];
    const float* ln1b = (const float*)d_in[17];
    const float* ln2g = (const float*)d_in[18];
    const float* ln2b = (const float*)d_in[19];
    const float* lnfg = (const float*)d_in[20];
    const float* lnfb = (const float*)d_in[21];
    const float* Wp   = (const float*)d_in[22];
    const float* bp   = (const float*)d_in[23];
    float* out = (float*)d_out;

    float *h, *t2, *sg;
    __nv_bfloat16 *hh, *hl, *qh, *ql, *kh, *kl, *vh, *vl, *t1h, *t1l, *wh, *wl;
    cudaGetSymbolAddress((void**)&h,   g_h);
    cudaGetSymbolAddress((void**)&t2,  g_t2);
    cudaGetSymbolAddress((void**)&sg,  g_sig);
    cudaGetSymbolAddress((void**)&hh,  g_hh);
    cudaGetSymbolAddress((void**)&hl,  g_hl);
    cudaGetSymbolAddress((void**)&qh,  g_qh);
    cudaGetSymbolAddress((void**)&ql,  g_ql);
    cudaGetSymbolAddress((void**)&kh,  g_kh);
    cudaGetSymbolAddress((void**)&kl,  g_kl);
    cudaGetSymbolAddress((void**)&vh,  g_vh);
    cudaGetSymbolAddress((void**)&vl,  g_vl);
    cudaGetSymbolAddress((void**)&t1h, g_t1h);
    cudaGetSymbolAddress((void**)&t1l, g_t1l);
    cudaGetSymbolAddress((void**)&wh,  g_wh);
    cudaGetSymbolAddress((void**)&wl,  g_wl);

    cudaFuncSetAttribute(mgemm<false>, cudaFuncAttributeMaxDynamicSharedMemorySize, MG_SMEM);
    cudaFuncSetAttribute(mgemm<true>,  cudaFuncAttributeMaxDynamicSharedMemorySize, MG_SMEM);
    cudaFuncSetAttribute(fscores,      cudaFuncAttributeMaxDynamicSharedMemorySize, FS_SMEM);

    wconv_kernel<<<dim3(64, 18), 256>>>(Wq, Wk, Wv, Wo, W1, W2, wh, wl);
    embed_kernel<<<ROWS, DM>>>(x, ck, h, hh, hl);

    dim3 g1(64, 4, 1);
    dim3 g3(64, 4, 3);
    for (int i = 0; i < NL; i++) {
        size_t wbase = (size_t)i*6*262144;
        GemmJob jq = { wh + wbase + 0*262144, wl + wbase + 0*262144, bq + i*DM, nullptr, qh, ql };
        GemmJob jk = { wh + wbase + 1*262144, wl + wbase + 1*262144, bk + i*DM, nullptr, kh, kl };
        GemmJob jv = { wh + wbase + 2*262144, wl + wbase + 2*262144, bv + i*DM, nullptr, vh, vl };
        GemmJob jo = { wh + wbase + 3*262144, wl + wbase + 3*262144, bo + i*DM, t2, nullptr, nullptr };
        GemmJob jf1 = { wh + wbase + 4*262144, wl + wbase + 4*262144, b1 + i*DM, nullptr, t1h, t1l };
        GemmJob jf2 = { wh + wbase + 5*262144, wl + wbase + 5*262144, b2 + i*DM, t2, nullptr, nullptr };

        mgemm<false><<<g3, 256, MG_SMEM>>>(hh, hl, jq, jk, jv);
        sig4_kernel<<<ROWS/4, 128>>>(h, Ws + (size_t)i*DM*NH, bs + i*NH, sg);

        float* ser = out + SERIES_OFF + (size_t)i*LAYER_ELEMS;
        fscores<<<dim3(8, 64), 512, FS_SMEM>>>(qh, ql, kh, kl, vh, vl, ser, t1h, t1l);
        prior_kernel<<<BATCH*NH*WIN, 128>>>(sg,
                out + PRIOR_OFF + (size_t)i*LAYER_ELEMS,
                out + SIGMA_OFF + (size_t)i*LAYER_ELEMS);

        mgemm<false><<<g1, 256, MG_SMEM>>>(t1h, t1l, jo, jo, jo);
        ln_kernel<<<ROWS, 256>>>(h, t2, ln1g + i*DM, ln1b + i*DM, h, hh, hl);

        mgemm<true ><<<g1, 256, MG_SMEM>>>(hh, hl, jf1, jf1, jf1);
        mgemm<false><<<g1, 256, MG_SMEM>>>(t1h, t1l, jf2, jf2, jf2);
        ln_kernel<<<ROWS, 256>>>(h, t2, ln2g + i*DM, ln2b + i*DM, h, hh, hl);
    }

    lnproj_kernel<<<ROWS, 256>>>(h, lnfg, lnfb, Wp, bp, out);
}

// round 16
// speedup vs baseline: 1.0072x; 1.0072x over previous
#include <cuda_runtime.h>
#include <cuda_bf16.h>
#include <math.h>
#include <stdint.h>

#define WIN   512
#define BATCH 8
#define CIN   38
#define COUT  38
#define DM    512
#define NH    8
#define EHD   64
#define NL    3
#define ROWS  (BATCH*WIN)   /* 4096 */

#define OUT_ELEMS    (BATCH*WIN*COUT)
#define LAYER_ELEMS  ((size_t)BATCH*NH*WIN*WIN)
#define SERIES_OFF   ((size_t)OUT_ELEMS)
#define PRIOR_OFF    (SERIES_OFF + 3*LAYER_ELEMS)
#define SIGMA_OFF    (PRIOR_OFF  + 3*LAYER_ELEMS)

// ---------------- scratch ---------------------------------------------------
__device__ float g_h [ROWS*DM];
__device__ float g_t2[ROWS*DM];
__device__ float g_sig[ROWS*NH];
__device__ __nv_bfloat16 g_hh [ROWS*DM];
__device__ __nv_bfloat16 g_hl [ROWS*DM];
__device__ __nv_bfloat16 g_qh [ROWS*DM];
__device__ __nv_bfloat16 g_ql [ROWS*DM];
__device__ __nv_bfloat16 g_kh [ROWS*DM];
__device__ __nv_bfloat16 g_kl [ROWS*DM];
__device__ __nv_bfloat16 g_vh [ROWS*DM];
__device__ __nv_bfloat16 g_vl [ROWS*DM];
__device__ __nv_bfloat16 g_t1h[ROWS*DM];
__device__ __nv_bfloat16 g_t1l[ROWS*DM];
__device__ __nv_bfloat16 g_wh [18*262144];   // TRANSPOSED [N,K] hi planes
__device__ __nv_bfloat16 g_wl [18*262144];   // TRANSPOSED [N,K] lo planes

// ---------------- helpers ---------------------------------------------------
__device__ __forceinline__ uint32_t smaddr(const void* p) {
    return (uint32_t)__cvta_generic_to_shared(p);
}
__device__ __forceinline__ void ldsm4(uint32_t a, uint32_t& r0, uint32_t& r1,
                                      uint32_t& r2, uint32_t& r3) {
    asm volatile("ldmatrix.sync.aligned.m8n8.x4.shared.b16 {%0,%1,%2,%3}, [%4];\n"
                 : "=r"(r0), "=r"(r1), "=r"(r2), "=r"(r3) : "r"(a));
}
__device__ __forceinline__ void ldsm2t(uint32_t a, uint32_t& r0, uint32_t& r1) {
    asm volatile("ldmatrix.sync.aligned.m8n8.x2.trans.shared.b16 {%0,%1}, [%2];\n"
                 : "=r"(r0), "=r"(r1) : "r"(a));
}
__device__ __forceinline__ void mmabf(float* d, const uint32_t* a, uint32_t b0, uint32_t b1) {
    asm volatile("mma.sync.aligned.m16n8k16.row.col.f32.bf16.bf16.f32 "
                 "{%0,%1,%2,%3}, {%4,%5,%6,%7}, {%8,%9}, {%0,%1,%2,%3};\n"
                 : "+f"(d[0]), "+f"(d[1]), "+f"(d[2]), "+f"(d[3])
                 : "r"(a[0]), "r"(a[1]), "r"(a[2]), "r"(a[3]), "r"(b0), "r"(b1));
}
__device__ __forceinline__ void cvst(float x, float y, __nv_bfloat16* ph, __nv_bfloat16* pl) {
    __nv_bfloat16 h0 = __float2bfloat16_rn(x);
    __nv_bfloat16 l0 = __float2bfloat16_rn(x - __bfloat162float(h0));
    __nv_bfloat16 h1 = __float2bfloat16_rn(y);
    __nv_bfloat16 l1 = __float2bfloat16_rn(y - __bfloat162float(h1));
    *(__nv_bfloat162*)ph = __halves2bfloat162(h0, h1);
    *(__nv_bfloat162*)pl = __halves2bfloat162(l0, l1);
}
__device__ __forceinline__ void cvst1(float x, __nv_bfloat16* ph, __nv_bfloat16* pl) {
    __nv_bfloat16 h0 = __float2bfloat16_rn(x);
    *ph = h0;
    *pl = __float2bfloat16_rn(x - __bfloat162float(h0));
}
__device__ __forceinline__ void cpa16(uint32_t s, const void* g) {
    asm volatile("cp.async.ca.shared.global [%0], [%1], 16;\n" :: "r"(s), "l"(g));
}

// ---------------- weight pre-conversion: transpose to [N,K] + split ---------
__global__ __launch_bounds__(256)
void wconv_kernel(const float* __restrict__ Wq, const float* __restrict__ Wk,
                  const float* __restrict__ Wv, const float* __restrict__ Wo,
                  const float* __restrict__ W1, const float* __restrict__ W2,
                  __nv_bfloat16* __restrict__ wh, __nv_bfloat16* __restrict__ wl) {
    __shared__ float tile[64][65];
    int m = blockIdx.y;               // 0..17
    int u = m % 6, i = m / 6;
    const float* src;
    switch (u) { case 0: src=Wq; break; case 1: src=Wk; break; case 2: src=Wv; break;
                 case 3: src=Wo; break; case 4: src=W1; break; default: src=W2; }
    src += (size_t)i * 262144;
    int t = blockIdx.x;               // 0..63
    int k0 = (t >> 3) * 64, n0 = (t & 7) * 64;
    int tid = threadIdx.x;
    for (int idx = tid; idx < 4096; idx += 256) {
        int r = idx >> 6, c = idx & 63;
        tile[r][c] = src[(size_t)(k0 + r)*512 + n0 + c];   // tile[k][n]
    }
    __syncthreads();
    __nv_bfloat16* dh = wh + (size_t)m * 262144;
    __nv_bfloat16* dl = wl + (size_t)m * 262144;
    for (int idx = tid; idx < 4096; idx += 256) {
        int r = idx >> 6, c = idx & 63;     // r = n-local, c = k-local
        cvst1(tile[c][r], dh + (size_t)(n0 + r)*512 + k0 + c,
                          dl + (size_t)(n0 + r)*512 + k0 + c);
    }
}

// ---------------- embedding -------------------------------------------------
__global__ void embed_kernel(const float* __restrict__ x,
                             const float* __restrict__ ck,
                             float* __restrict__ h,
                             __nv_bfloat16* __restrict__ hh,
                             __nv_bfloat16* __restrict__ hl) {
    int bt = blockIdx.x;
    int b = bt >> 9, t = bt & (WIN-1);
    __shared__ float xs[3*CIN];
    int tid = threadIdx.x;
    if (tid < 3*CIN) {
        int w = tid / CIN, c = tid % CIN;
        int src = (t + w - 1 + WIN) & (WIN-1);
        xs[tid] = x[((size_t)b*WIN + src)*CIN + c];
    }
    __syncthreads();
    int d = tid;
    int i2 = (d >> 1) * 2;
    float ang = (float)t * __expf(-(float)i2 * (9.210340371976184f/512.0f));
    float acc = (d & 1) ? cosf(ang) : sinf(ang);
#pragma unroll 1
    for (int wc = 0; wc < 3*CIN; wc++)
        acc += xs[wc] * ck[(size_t)wc*DM + d];
    size_t idx = (size_t)bt*DM + d;
    h[idx] = acc;
    cvst1(acc, hh + idx, hl + idx);
}

// ---------------- dense GEMM: 64x128, [N,K] weights, no trans ldsm ----------
struct GemmJob {
    const __nv_bfloat16* Wh; const __nv_bfloat16* Wl;   // transposed [N,K]
    const float* bias;
    float* Cf; __nv_bfloat16* Ch; __nv_bfloat16* Cl;
};

#define AH_OFF 0
#define AL_OFF 2560
#define BH_OFF 5120
#define BL_OFF 10240
#define BUF_SZ 15360   /* halves per buffer */
#define MG_SMEM (2*BUF_SZ*2)   /* 61440 B */

__device__ __forceinline__ void mg_issue(uint32_t smb, int buf, int tid,
        const __nv_bfloat16* Ah, const __nv_bfloat16* Al,
        const __nv_bfloat16* Wh, const __nv_bfloat16* Wl, int kt) {
    uint32_t base = smb + (uint32_t)buf * (BUF_SZ*2);
    // A: 64 rows x 32 k-halves, stride 40
    int ar = tid >> 2, ac = (tid & 3) * 8;
    const __nv_bfloat16* ga  = Ah + (size_t)ar*512 + kt*32 + ac;
    const __nv_bfloat16* gal = Al + (size_t)ar*512 + kt*32 + ac;
    cpa16(base + (uint32_t)(AH_OFF + ar*40 + ac)*2, ga);
    cpa16(base + (uint32_t)(AL_OFF + ar*40 + ac)*2, gal);
    // B ([N,K]): 128 n-rows x 32 k-halves, stride 40
    int br = tid >> 1, bc = (tid & 1) * 16;
    const __nv_bfloat16* gb  = Wh + (size_t)br*512 + kt*32 + bc;
    const __nv_bfloat16* gbl = Wl + (size_t)br*512 + kt*32 + bc;
    uint32_t sb  = base + (uint32_t)(BH_OFF + br*40 + bc)*2;
    uint32_t sbl = base + (uint32_t)(BL_OFF + br*40 + bc)*2;
    cpa16(sb, gb);        cpa16(sb+16, gb+8);
    cpa16(sbl, gbl);      cpa16(sbl+16, gbl+8);
    asm volatile("cp.async.commit_group;\n");
}

__device__ __forceinline__ void mg_compute(uint32_t smb, int buf, int tid,
                                           float (*acc)[4][4]) {
    int l = tid & 31, w = tid >> 5, wm = w & 1, wn = w >> 1;
    int lr = l & 15, lc8 = (l >> 4) << 3;
    uint32_t base = smb + (uint32_t)buf * (BUF_SZ*2);
#pragma unroll
    for (int ks = 0; ks < 32; ks += 16) {
        uint32_t ah[2][4], al[2][4];
#pragma unroll
        for (int fm = 0; fm < 2; fm++) {
            uint32_t aoff = (uint32_t)((wm*32 + fm*16 + lr)*40 + ks + lc8) * 2;
            ldsm4(base + AH_OFF*2 + aoff, ah[fm][0], ah[fm][1], ah[fm][2], ah[fm][3]);
            ldsm4(base + AL_OFF*2 + aoff, al[fm][0], al[fm][1], al[fm][2], al[fm][3]);
        }
#pragma unroll
        for (int fnp = 0; fnp < 2; fnp++) {
            // non-trans B: n-major rows, K-contiguous (same pattern as scores K)
            uint32_t boff = (uint32_t)((wn*32 + fnp*16 + lr)*40 + ks + lc8) * 2;
            uint32_t bh[4], bl[4];
            ldsm4(base + BH_OFF*2 + boff, bh[0], bh[1], bh[2], bh[3]);
            ldsm4(base + BL_OFF*2 + boff, bl[0], bl[1], bl[2], bl[3]);
#pragma unroll
            for (int fm = 0; fm < 2; fm++) {
                mmabf(acc[fm][fnp*2],   ah[fm], bh[0], bh[2]);
                mmabf(acc[fm][fnp*2],   ah[fm], bl[0], bl[2]);
                mmabf(acc[fm][fnp*2],   al[fm], bh[0], bh[2]);
                mmabf(acc[fm][fnp*2+1], ah[fm], bh[1], bh[3]);
                mmabf(acc[fm][fnp*2+1], ah[fm], bl[1], bl[3]);
                mmabf(acc[fm][fnp*2+1], al[fm], bh[1], bh[3]);
            }
        }
    }
}

template<bool GELU>
__global__ __launch_bounds__(256, 3)
void mgemm(const __nv_bfloat16* __restrict__ Ah, const __nv_bfloat16* __restrict__ Al,
           GemmJob j0, GemmJob j1, GemmJob j2) {
    extern __shared__ __nv_bfloat16 sm[];
    GemmJob jb = (blockIdx.z == 0) ? j0 : ((blockIdx.z == 1) ? j1 : j2);
    int tid = threadIdx.x;
    const __nv_bfloat16* Abh = Ah + (size_t)blockIdx.x * 64 * 512;
    const __nv_bfloat16* Abl = Al + (size_t)blockIdx.x * 64 * 512;
    const __nv_bfloat16* Wbh = jb.Wh + (size_t)blockIdx.y * 128 * 512;  // [N,K]
    const __nv_bfloat16* Wbl = jb.Wl + (size_t)blockIdx.y * 128 * 512;
    uint32_t smb = smaddr(sm);

    mg_issue(smb, 0, tid, Abh, Abl, Wbh, Wbl, 0);
    mg_issue(smb, 1, tid, Abh, Abl, Wbh, Wbl, 1);

    float acc[2][4][4] = {};
    for (int kt = 0; kt < 16; kt++) {
        int buf = kt & 1;
        if (kt < 15) asm volatile("cp.async.wait_group 1;\n");
        else         asm volatile("cp.async.wait_group 0;\n");
        __syncthreads();
        mg_compute(smb, buf, tid, acc);
        if (kt < 14) {
            __syncthreads();
            mg_issue(smb, buf, tid, Abh, Abl, Wbh, Wbl, kt+2);
        }
    }

    int l = tid & 31, w = tid >> 5, wm = w & 1, wn = w >> 1;
    int g = l >> 2, t2 = (l & 3) * 2;
    int rowb = blockIdx.x*64 + wm*32;
    int colb = blockIdx.y*128 + wn*32;
#pragma unroll
    for (int fm = 0; fm < 2; fm++) {
#pragma unroll
        for (int fn = 0; fn < 4; fn++) {
            int col = colb + fn*8 + t2;
            float bx0 = jb.bias[col], bx1 = jb.bias[col+1];
            float o0 = acc[fm][fn][0] + bx0, o1 = acc[fm][fn][1] + bx1;
            float o2 = acc[fm][fn][2] + bx0, o3 = acc[fm][fn][3] + bx1;
            if (GELU) {
                o0 = 0.5f*o0*(1.0f + erff(o0*0.70710678118654752f));
                o1 = 0.5f*o1*(1.0f + erff(o1*0.70710678118654752f));
                o2 = 0.5f*o2*(1.0f + erff(o2*0.70710678118654752f));
                o3 = 0.5f*o3*(1.0f + erff(o3*0.70710678118654752f));
            }
            int r0 = rowb + fm*16 + g;
            if (jb.Cf) {
                float2 p0 = {o0, o1}, p1 = {o2, o3};
                *(float2*)(jb.Cf + (size_t)r0*512 + col)     = p0;
                *(float2*)(jb.Cf + (size_t)(r0+8)*512 + col) = p1;
            }
            if (jb.Ch) {
                cvst(o0, o1, jb.Ch + (size_t)r0*512 + col,     jb.Cl + (size_t)r0*512 + col);
                cvst(o2, o3, jb.Ch + (size_t)(r0+8)*512 + col, jb.Cl + (size_t)(r0+8)*512 + col);
            }
        }
    }
}

// ---------------- fused scores + softmax + S@V ------------------------------
#define FQH 0
#define FQL 4608
#define FKH 9216
#define FKL 46080
#define FVH 0
#define FVL 4608
#define FSH 9216
#define FSL 42496
#define FS_SMEM 165888

__global__ __launch_bounds__(512)
void fscores(const __nv_bfloat16* __restrict__ qh, const __nv_bfloat16* __restrict__ ql,
             const __nv_bfloat16* __restrict__ kh, const __nv_bfloat16* __restrict__ kl,
             const __nv_bfloat16* __restrict__ vh, const __nv_bfloat16* __restrict__ vl,
             float* __restrict__ out,
             __nv_bfloat16* __restrict__ t1h, __nv_bfloat16* __restrict__ t1l) {
    extern __shared__ __nv_bfloat16 sm[];
    __shared__ float red[64][8];
    int tid = threadIdx.x;
    int bh = blockIdx.y, b = bh >> 3, hhd = bh & 7;
    int l0 = blockIdx.x * 64;

    {
        int r = tid >> 3, c = (tid & 7) * 8;
        size_t qoff = ((size_t)(b*512 + l0 + r))*512 + hhd*64 + c;
        int qi = r*72 + c;
        *(uint4*)&sm[FQH + qi] = *(const uint4*)(qh + qoff);
        *(uint4*)&sm[FQL + qi] = *(const uint4*)(ql + qoff);
#pragma unroll
        for (int i = 0; i < 8; i++) {
            int kr = r + i*64;
            size_t koff = ((size_t)(b*512 + kr))*512 + hhd*64 + c;
            int ki = kr*72 + c;
            *(uint4*)&sm[FKH + ki] = *(const uint4*)(kh + koff);
            *(uint4*)&sm[FKL + ki] = *(const uint4*)(kl + koff);
        }
    }
    __syncthreads();

    uint32_t smb = smaddr(sm);
    int l = tid & 31, w = tid >> 5;
    int wn = w & 7, wm = w >> 3;
    int lr = l & 15, lc8 = (l >> 4) << 3;
    float acc[2][8][4] = {};
#pragma unroll
    for (int ks = 0; ks < 64; ks += 16) {
        uint32_t ah[2][4], al[2][4];
#pragma unroll
        for (int fm = 0; fm < 2; fm++) {
            uint32_t aoff = (uint32_t)((wm*32 + fm*16 + lr)*72 + ks + lc8) * 2;
            ldsm4(smb + FQH*2 + aoff, ah[fm][0], ah[fm][1], ah[fm][2], ah[fm][3]);
            ldsm4(smb + FQL*2 + aoff, al[fm][0], al[fm][1], al[fm][2], al[fm][3]);
        }
#pragma unroll
        for (int fnp = 0; fnp < 4; fnp++) {
            uint32_t boff = (uint32_t)((wn*64 + fnp*16 + lr)*72 + ks + lc8) * 2;
            uint32_t khr[4], klr[4];
            ldsm4(smb + FKH*2 + boff, khr[0], khr[1], khr[2], khr[3]);
            ldsm4(smb + FKL*2 + boff, klr[0], klr[1], klr[2], klr[3]);
#pragma unroll
            for (int fm = 0; fm < 2; fm++) {
                mmabf(acc[fm][fnp*2],   ah[fm], khr[0], khr[2]);
                mmabf(acc[fm][fnp*2],   ah[fm], klr[0], klr[2]);
                mmabf(acc[fm][fnp*2],   al[fm], khr[0], khr[2]);
                mmabf(acc[fm][fnp*2+1], ah[fm], khr[1], khr[3]);
                mmabf(acc[fm][fnp*2+1], ah[fm], klr[1], klr[3]);
                mmabf(acc[fm][fnp*2+1], al[fm], khr[1], khr[3]);
            }
        }
    }

#pragma unroll
    for (int fm = 0; fm < 2; fm++)
#pragma unroll
        for (int fn = 0; fn < 8; fn++)
#pragma unroll
            for (int e = 0; e < 4; e++) acc[fm][fn][e] *= 0.125f;

    int g = l >> 2, t2 = (l & 3) * 2;
    float tmax[2][2] = {{-1e30f,-1e30f},{-1e30f,-1e30f}};
#pragma unroll
    for (int fm = 0; fm < 2; fm++)
#pragma unroll
        for (int fn = 0; fn < 8; fn++) {
            tmax[fm][0] = fmaxf(tmax[fm][0], fmaxf(acc[fm][fn][0], acc[fm][fn][1]));
            tmax[fm][1] = fmaxf(tmax[fm][1], fmaxf(acc[fm][fn][2], acc[fm][fn][3]));
        }
#pragma unroll
    for (int o = 1; o <= 2; o <<= 1) {
#pragma unroll
        for (int fm = 0; fm < 2; fm++) {
            tmax[fm][0] = fmaxf(tmax[fm][0], __shfl_xor_sync(0xffffffff, tmax[fm][0], o));
            tmax[fm][1] = fmaxf(tmax[fm][1], __shfl_xor_sync(0xffffffff, tmax[fm][1], o));
        }
    }
    if ((l & 3) == 0) {
#pragma unroll
        for (int fm = 0; fm < 2; fm++) {
            red[wm*32 + fm*16 + g][wn]     = tmax[fm][0];
            red[wm*32 + fm*16 + g + 8][wn] = tmax[fm][1];
        }
    }
    __syncthreads();
    float rmax[2][2];
#pragma unroll
    for (int fm = 0; fm < 2; fm++)
#pragma unroll
        for (int hf = 0; hf < 2; hf++) {
            int r = wm*32 + fm*16 + g + hf*8;
            float m = red[r][0];
#pragma unroll
            for (int ww = 1; ww < 8; ww++) m = fmaxf(m, red[r][ww]);
            rmax[fm][hf] = m;
        }
    __syncthreads();

    float tsum[2][2] = {};
#pragma unroll
    for (int fm = 0; fm < 2; fm++)
#pragma unroll
        for (int fn = 0; fn < 8; fn++) {
            acc[fm][fn][0] = __expf(acc[fm][fn][0] - rmax[fm][0]);
            acc[fm][fn][1] = __expf(acc[fm][fn][1] - rmax[fm][0]);
            acc[fm][fn][2] = __expf(acc[fm][fn][2] - rmax[fm][1]);
            acc[fm][fn][3] = __expf(acc[fm][fn][3] - rmax[fm][1]);
            tsum[fm][0] += acc[fm][fn][0] + acc[fm][fn][1];
            tsum[fm][1] += acc[fm][fn][2] + acc[fm][fn][3];
        }
#pragma unroll
    for (int o = 1; o <= 2; o <<= 1) {
#pragma unroll
        for (int fm = 0; fm < 2; fm++) {
            tsum[fm][0] += __shfl_xor_sync(0xffffffff, tsum[fm][0], o);
            tsum[fm][1] += __shfl_xor_sync(0xffffffff, tsum[fm][1], o);
        }
    }
    if ((l & 3) == 0) {
#pragma unroll
        for (int fm = 0; fm < 2; fm++) {
            red[wm*32 + fm*16 + g][wn]     = tsum[fm][0];
            red[wm*32 + fm*16 + g + 8][wn] = tsum[fm][1];
        }
    }
    __syncthreads();
    float rinv[2][2];
#pragma unroll
    for (int fm = 0; fm < 2; fm++)
#pragma unroll
        for (int hf = 0; hf < 2; hf++) {
            int r = wm*32 + fm*16 + g + hf*8;
            float s = red[r][0];
#pragma unroll
            for (int ww = 1; ww < 8; ww++) s += red[r][ww];
            rinv[fm][hf] = 1.0f / s;
        }

    float* ob = out + ((size_t)bh*512 + l0)*512;
#pragma unroll
    for (int fm = 0; fm < 2; fm++)
#pragma unroll
        for (int fn = 0; fn < 8; fn++) {
            int row0 = wm*32 + fm*16 + g;
            int col = wn*64 + fn*8 + t2;
            float s0 = acc[fm][fn][0]*rinv[fm][0], s1 = acc[fm][fn][1]*rinv[fm][0];
            float s2 = acc[fm][fn][2]*rinv[fm][1], s3 = acc[fm][fn][3]*rinv[fm][1];
            float2 p0 = {s0, s1}, p1 = {s2, s3};
            *(float2*)(ob + (size_t)row0*512 + col)     = p0;
            *(float2*)(ob + (size_t)(row0+8)*512 + col) = p1;
            cvst(s0, s1, &sm[FSH + row0*520 + col],     &sm[FSL + row0*520 + col]);
            cvst(s2, s3, &sm[FSH + (row0+8)*520 + col], &sm[FSL + (row0+8)*520 + col]);
        }
    __syncthreads();

    float acc2[2][4] = {};
    for (int kc = 0; kc < 8; kc++) {
        {
            int r = tid >> 3, c = (tid & 7) * 8;
            size_t voff = ((size_t)(b*512 + kc*64 + r))*512 + hhd*64 + c;
            *(uint4*)&sm[FVH + r*72 + c] = *(const uint4*)(vh + voff);
            *(uint4*)&sm[FVL + r*72 + c] = *(const uint4*)(vl + voff);
        }
        __syncthreads();
#pragma unroll
        for (int ks = 0; ks < 64; ks += 16) {
            uint32_t sa[2][4], sl2[2][4];
#pragma unroll
            for (int fm = 0; fm < 2; fm++) {
                uint32_t aoff = (uint32_t)((wm*32 + fm*16 + lr)*520 + kc*64 + ks + lc8) * 2;
                ldsm4(smb + FSH*2 + aoff, sa[fm][0], sa[fm][1], sa[fm][2], sa[fm][3]);
                ldsm4(smb + FSL*2 + aoff, sl2[fm][0], sl2[fm][1], sl2[fm][2], sl2[fm][3]);
            }
            uint32_t boff = (uint32_t)((ks + lr)*72 + wn*8) * 2;
            uint32_t bh2[2], bl2[2];
            ldsm2t(smb + FVH*2 + boff, bh2[0], bh2[1]);
            ldsm2t(smb + FVL*2 + boff, bl2[0], bl2[1]);
#pragma unroll
            for (int fm = 0; fm < 2; fm++) {
                mmabf(acc2[fm], sa[fm],  bh2[0], bh2[1]);
                mmabf(acc2[fm], sa[fm],  bl2[0], bl2[1]);
                mmabf(acc2[fm], sl2[fm], bh2[0], bh2[1]);
            }
        }
        if (kc < 7) __syncthreads();
    }

#pragma unroll
    for (int fm = 0; fm < 2; fm++) {
        int row0 = wm*32 + fm*16 + g;
        int col = wn*8 + t2;
        size_t p0 = ((size_t)(b*512 + l0 + row0))*512 + hhd*64 + col;
        size_t p1 = ((size_t)(b*512 + l0 + row0 + 8))*512 + hhd*64 + col;
        cvst(acc2[fm][0], acc2[fm][1], t1h + p0, t1l + p0);
        cvst(acc2[fm][2], acc2[fm][3], t1h + p1, t1l + p1);
    }
}

// ---------------- sigma projection ------------------------------------------
__global__ __launch_bounds__(128)
void sig4_kernel(const float* __restrict__ h, const float* __restrict__ Ws,
                 const float* __restrict__ bs, float* __restrict__ sig) {
    int warp = threadIdx.x >> 5, lane = threadIdx.x & 31;
    int row = blockIdx.x*4 + warp;
    const float* hr = h + (size_t)row*512;
    float s[8] = {};
#pragma unroll
    for (int i = 0; i < 16; i++) {
        int k = i*32 + lane;
        float hv = hr[k];
        float4 wa = *(const float4*)(Ws + k*8);
        float4 wb = *(const float4*)(Ws + k*8 + 4);
        s[0] += hv*wa.x; s[1] += hv*wa.y; s[2] += hv*wa.z; s[3] += hv*wa.w;
        s[4] += hv*wb.x; s[5] += hv*wb.y; s[6] += hv*wb.z; s[7] += hv*wb.w;
    }
#pragma unroll
    for (int off = 16; off > 0; off >>= 1)
#pragma unroll
        for (int o = 0; o < 8; o++) s[o] += __shfl_xor_sync(0xffffffff, s[o], off);
    if (lane < 8) sig[row*8 + lane] = s[lane] + bs[lane];
}

// ---------------- prior + sigma ---------------------------------------------
__global__ __launch_bounds__(128)
void prior_kernel(const float* __restrict__ sig,
                  float* __restrict__ prior, float* __restrict__ sigma) {
    int idx = blockIdx.x;
    int l = idx & (WIN-1);
    int bh = idx >> 9;
    int b = bh >> 3, hh = bh & 7;
    float sv = sig[((size_t)b*WIN + l)*NH + hh];
    float sgm = 1.0f/(1.0f + __expf(-5.0f*sv)) + 1e-5f;
    float sg  = __expf(sgm * 1.0986122886681098f) - 1.0f;
    float inv = 0.3989422804014327f / sg;
    float cc  = -1.0f/(2.0f*sg*sg);
    size_t base = ((size_t)bh*WIN + l)*WIN;
    int s0 = threadIdx.x * 4;
    float d0 = (float)(l - s0), d1 = d0 - 1.0f, d2 = d0 - 2.0f, d3 = d0 - 3.0f;
    float4 pr;
    pr.x = inv*__expf(cc*d0*d0); pr.y = inv*__expf(cc*d1*d1);
    pr.z = inv*__expf(cc*d2*d2); pr.w = inv*__expf(cc*d3*d3);
    *(float4*)(prior + base + s0) = pr;
    float4 sgv = {sg, sg, sg, sg};
    *(float4*)(sigma + base + s0) = sgv;
}

// ---------------- LayerNorm -------------------------------------------------
__global__ void ln_kernel(const float* __restrict__ x, const float* __restrict__ res,
                          const float* __restrict__ g, const float* __restrict__ bb,
                          float* __restrict__ outf,
                          __nv_bfloat16* __restrict__ outh, __nv_bfloat16* __restrict__ outl) {
    size_t row = blockIdx.x;
    int tid = threadIdx.x;
    const float* xr = x + row*DM;
    float v0 = xr[tid], v1 = xr[tid+256];
    if (res) { const float* rr = res + row*DM; v0 += rr[tid]; v1 += rr[tid+256]; }
    __shared__ float red[256];
    red[tid] = v0 + v1;
    __syncthreads();
    for (int s = 128; s > 0; s >>= 1) { if (tid < s) red[tid] += red[tid+s]; __syncthreads(); }
    float mu = red[0] * (1.0f/DM);
    __syncthreads();
    float d0 = v0 - mu, d1 = v1 - mu;
    red[tid] = d0*d0 + d1*d1;
    __syncthreads();
    for (int s = 128; s > 0; s >>= 1) { if (tid < s) red[tid] += red[tid+s]; __syncthreads(); }
    float r = rsqrtf(red[0]*(1.0f/DM) + 1e-3f);
    float y0 = d0*r*g[tid]     + bb[tid];
    float y1 = d1*r*g[tid+256] + bb[tid+256];
    size_t i0 = row*DM + tid, i1 = i0 + 256;
    outf[i0] = y0;
    outf[i1] = y1;
    if (outh) {
        cvst1(y0, outh + i0, outl + i0);
        cvst1(y1, outh + i1, outl + i1);
    }
}

// ---------------- fused final LayerNorm + projection -------------------------
__global__ void lnproj_kernel(const float* __restrict__ x,
                              const float* __restrict__ g, const float* __restrict__ bb,
                              const float* __restrict__ Wp, const float* __restrict__ bp,
                              float* __restrict__ out) {
    __shared__ float hs[512];
    __shared__ float red[256];
    size_t row = blockIdx.x;
    int tid = threadIdx.x;
    const float* xr = x + row*DM;
    float v0 = xr[tid], v1 = xr[tid+256];
    red[tid] = v0 + v1;
    __syncthreads();
    for (int s = 128; s > 0; s >>= 1) { if (tid < s) red[tid] += red[tid+s]; __syncthreads(); }
    float mu = red[0] * (1.0f/DM);
    __syncthreads();
    float d0 = v0 - mu, d1 = v1 - mu;
    red[tid] = d0*d0 + d1*d1;
    __syncthreads();
    for (int s = 128; s > 0; s >>= 1) { if (tid < s) red[tid] += red[tid+s]; __syncthreads(); }
    float r = rsqrtf(red[0]*(1.0f/DM) + 1e-3f);
    hs[tid]     = d0*r*g[tid]     + bb[tid];
    hs[tid+256] = d1*r*g[tid+256] + bb[tid+256];
    __syncthreads();
    int warp = tid >> 5, lane = tid & 31;
    for (int c = warp; c < COUT; c += 8) {
        float sum = 0.f;
#pragma unroll
        for (int k2 = lane; k2 < 512; k2 += 32) sum += hs[k2] * Wp[(size_t)k2*COUT + c];
#pragma unroll
        for (int o = 16; o > 0; o >>= 1) sum += __shfl_xor_sync(0xffffffff, sum, o);
        if (lane == 0) out[row*COUT + c] = sum + bp[c];
    }
}

// ---------------- host orchestration ----------------------------------------
extern "C" void kernel_launch(void* const* d_in, const int* in_sizes, int n_in,
                              void* d_out, int out_size) {
    const float* x    = (const float*)d_in[0];
    const float* ck   = (const float*)d_in[1];
    const float* Wq   = (const float*)d_in[2];
    const float* bq   = (const float*)d_in[3];
    const float* Wk   = (const float*)d_in[4];
    const float* bk   = (const float*)d_in[5];
    const float* Wv   = (const float*)d_in[6];
    const float* bv   = (const float*)d_in[7];
    const float* Ws   = (const float*)d_in[8];
    const float* bs   = (const float*)d_in[9];
    const float* Wo   = (const float*)d_in[10];
    const float* bo   = (const float*)d_in[11];
    const float* W1   = (const float*)d_in[12];
    const float* b1   = (const float*)d_in[13];
    const float* W2   = (const float*)d_in[14];
    const float* b2   = (const float*)d_in[15];
    const float* ln1g = (const float*)d_in[16];
    const float* ln1b = (const float*)d_in[17];
    const float* ln2g = (const float*)d_in[18];
    const float* ln2b = (const float*)d_in[19];
    const float* lnfg = (const float*)d_in[20];
    const float* lnfb = (const float*)d_in[21];
    const float* Wp   = (const float*)d_in[22];
    const float* bp   = (const float*)d_in[23];
    float* out = (float*)d_out;

    float *h, *t2, *sg;
    __nv_bfloat16 *hh, *hl, *qh, *ql, *kh, *kl, *vh, *vl, *t1h, *t1l, *wh, *wl;
    cudaGetSymbolAddress((void**)&h,   g_h);
    cudaGetSymbolAddress((void**)&t2,  g_t2);
    cudaGetSymbolAddress((void**)&sg,  g_sig);
    cudaGetSymbolAddress((void**)&hh,  g_hh);
    cudaGetSymbolAddress((void**)&hl,  g_hl);
    cudaGetSymbolAddress((void**)&qh,  g_qh);
    cudaGetSymbolAddress((void**)&ql,  g_ql);
    cudaGetSymbolAddress((void**)&kh,  g_kh);
    cudaGetSymbolAddress((void**)&kl,  g_kl);
    cudaGetSymbolAddress((void**)&vh,  g_vh);
    cudaGetSymbolAddress((void**)&vl,  g_vl);
    cudaGetSymbolAddress((void**)&t1h, g_t1h);
    cudaGetSymbolAddress((void**)&t1l, g_t1l);
    cudaGetSymbolAddress((void**)&wh,  g_wh);
    cudaGetSymbolAddress((void**)&wl,  g_wl);

    cudaFuncSetAttribute(mgemm<false>, cudaFuncAttributeMaxDynamicSharedMemorySize, MG_SMEM);
    cudaFuncSetAttribute(mgemm<true>,  cudaFuncAttributeMaxDynamicSharedMemorySize, MG_SMEM);
    cudaFuncSetAttribute(fscores,      cudaFuncAttributeMaxDynamicSharedMemorySize, FS_SMEM);

    wconv_kernel<<<dim3(64, 18), 256>>>(Wq, Wk, Wv, Wo, W1, W2, wh, wl);
    embed_kernel<<<ROWS, DM>>>(x, ck, h, hh, hl);

    dim3 g1(64, 4, 1);
    dim3 g3(64, 4, 3);
    for (int i = 0; i < NL; i++) {
        size_t wbase = (size_t)i*6*262144;
        GemmJob jq = { wh + wbase + 0*262144, wl + wbase + 0*262144, bq + i*DM, nullptr, qh, ql };
        GemmJob jk = { wh + wbase + 1*262144, wl + wbase + 1*262144, bk + i*DM, nullptr, kh, kl };
        GemmJob jv = { wh + wbase + 2*262144, wl + wbase + 2*262144, bv + i*DM, nullptr, vh, vl };
        GemmJob jo = { wh + wbase + 3*262144, wl + wbase + 3*262144, bo + i*DM, t2, nullptr, nullptr };
        GemmJob jf1 = { wh + wbase + 4*262144, wl + wbase + 4*262144, b1 + i*DM, nullptr, t1h, t1l };
        GemmJob jf2 = { wh + wbase + 5*262144, wl + wbase + 5*262144, b2 + i*DM, t2, nullptr, nullptr };

        mgemm<false><<<g3, 256, MG_SMEM>>>(hh, hl, jq, jk, jv);
        sig4_kernel<<<ROWS/4, 128>>>(h, Ws + (size_t)i*DM*NH, bs + i*NH, sg);

        float* ser = out + SERIES_OFF + (size_t)i*LAYER_ELEMS;
        fscores<<<dim3(8, 64), 512, FS_SMEM>>>(qh, ql, kh, kl, vh, vl, ser, t1h, t1l);
        prior_kernel<<<BATCH*NH*WIN, 128>>>(sg,
                out + PRIOR_OFF + (size_t)i*LAYER_ELEMS,
                out + SIGMA_OFF + (size_t)i*LAYER_ELEMS);

        mgemm<false><<<g1, 256, MG_SMEM>>>(t1h, t1l, jo, jo, jo);
        ln_kernel<<<ROWS, 256>>>(h, t2, ln1g + i*DM, ln1b + i*DM, h, hh, hl);

        mgemm<true ><<<g1, 256, MG_SMEM>>>(hh, hl, jf1, jf1, jf1);
        mgemm<false><<<g1, 256, MG_SMEM>>>(t1h, t1l, jf2, jf2, jf2);
        ln_kernel<<<ROWS, 256>>>(h, t2, ln2g + i*DM, ln2b + i*DM, h, hh, hl);
    }

    lnproj_kernel<<<ROWS, 256>>>(h, lnfg, lnfb, Wp, bp, out);
}

// round 17
// speedup vs baseline: 1.1240x; 1.1160x over previous
#include <cuda_runtime.h>
#include <cuda_bf16.h>
#include <math.h>
#include <stdint.h>

#define WIN   512
#define BATCH 8
#define CIN   38
#define COUT  38
#define DM    512
#define NH    8
#define EHD   64
#define NL    3
#define ROWS  (BATCH*WIN)   /* 4096 */

#define OUT_ELEMS    (BATCH*WIN*COUT)
#define LAYER_ELEMS  ((size_t)BATCH*NH*WIN*WIN)
#define SERIES_OFF   ((size_t)OUT_ELEMS)
#define PRIOR_OFF    (SERIES_OFF + 3*LAYER_ELEMS)
#define SIGMA_OFF    (PRIOR_OFF  + 3*LAYER_ELEMS)

// ---------------- scratch ---------------------------------------------------
__device__ float g_h [ROWS*DM];
__device__ float g_t2[ROWS*DM];
__device__ float g_sig[ROWS*NH];
__device__ __nv_bfloat16 g_hh [ROWS*DM];
__device__ __nv_bfloat16 g_hl [ROWS*DM];
__device__ __nv_bfloat16 g_qh [ROWS*DM];
__device__ __nv_bfloat16 g_ql [ROWS*DM];
__device__ __nv_bfloat16 g_kh [ROWS*DM];
__device__ __nv_bfloat16 g_kl [ROWS*DM];
__device__ __nv_bfloat16 g_vh [ROWS*DM];
__device__ __nv_bfloat16 g_vl [ROWS*DM];
__device__ __nv_bfloat16 g_t1h[ROWS*DM];
__device__ __nv_bfloat16 g_t1l[ROWS*DM];
__device__ __nv_bfloat16 g_wh [18*262144];
__device__ __nv_bfloat16 g_wl [18*262144];

// ---------------- helpers ---------------------------------------------------
__device__ __forceinline__ uint32_t smaddr(const void* p) {
    return (uint32_t)__cvta_generic_to_shared(p);
}
__device__ __forceinline__ void ldsm4(uint32_t a, uint32_t& r0, uint32_t& r1,
                                      uint32_t& r2, uint32_t& r3) {
    asm volatile("ldmatrix.sync.aligned.m8n8.x4.shared.b16 {%0,%1,%2,%3}, [%4];\n"
                 : "=r"(r0), "=r"(r1), "=r"(r2), "=r"(r3) : "r"(a));
}
__device__ __forceinline__ void ldsm4t(uint32_t a, uint32_t& r0, uint32_t& r1,
                                       uint32_t& r2, uint32_t& r3) {
    asm volatile("ldmatrix.sync.aligned.m8n8.x4.trans.shared.b16 {%0,%1,%2,%3}, [%4];\n"
                 : "=r"(r0), "=r"(r1), "=r"(r2), "=r"(r3) : "r"(a));
}
__device__ __forceinline__ void ldsm2t(uint32_t a, uint32_t& r0, uint32_t& r1) {
    asm volatile("ldmatrix.sync.aligned.m8n8.x2.trans.shared.b16 {%0,%1}, [%2];\n"
                 : "=r"(r0), "=r"(r1) : "r"(a));
}
__device__ __forceinline__ void mmabf(float* d, const uint32_t* a, uint32_t b0, uint32_t b1) {
    asm volatile("mma.sync.aligned.m16n8k16.row.col.f32.bf16.bf16.f32 "
                 "{%0,%1,%2,%3}, {%4,%5,%6,%7}, {%8,%9}, {%0,%1,%2,%3};\n"
                 : "+f"(d[0]), "+f"(d[1]), "+f"(d[2]), "+f"(d[3])
                 : "r"(a[0]), "r"(a[1]), "r"(a[2]), "r"(a[3]), "r"(b0), "r"(b1));
}
__device__ __forceinline__ void cvst(float x, float y, __nv_bfloat16* ph, __nv_bfloat16* pl) {
    __nv_bfloat16 h0 = __float2bfloat16_rn(x);
    __nv_bfloat16 l0 = __float2bfloat16_rn(x - __bfloat162float(h0));
    __nv_bfloat16 h1 = __float2bfloat16_rn(y);
    __nv_bfloat16 l1 = __float2bfloat16_rn(y - __bfloat162float(h1));
    *(__nv_bfloat162*)ph = __halves2bfloat162(h0, h1);
    *(__nv_bfloat162*)pl = __halves2bfloat162(l0, l1);
}
__device__ __forceinline__ void cvst1(float x, __nv_bfloat16* ph, __nv_bfloat16* pl) {
    __nv_bfloat16 h0 = __float2bfloat16_rn(x);
    *ph = h0;
    *pl = __float2bfloat16_rn(x - __bfloat162float(h0));
}
__device__ __forceinline__ void cpa16(uint32_t s, const void* g) {
    asm volatile("cp.async.ca.shared.global [%0], [%1], 16;\n" :: "r"(s), "l"(g));
}
// block-wide sum of one value per thread (256 threads), 2 syncs
__device__ __forceinline__ float blocksum256(float v, float* ws, int tid) {
    int lane = tid & 31, warp = tid >> 5;
#pragma unroll
    for (int o = 16; o > 0; o >>= 1) v += __shfl_xor_sync(0xffffffff, v, o);
    if (lane == 0) ws[warp] = v;
    __syncthreads();
    float t = ws[0] + ws[1] + ws[2] + ws[3] + ws[4] + ws[5] + ws[6] + ws[7];
    __syncthreads();
    return t;
}

// ---------------- weight pre-conversion (plain split, [K,N] layout) ---------
__global__ void wconv_kernel(const float* __restrict__ Wq, const float* __restrict__ Wk,
                             const float* __restrict__ Wv, const float* __restrict__ Wo,
                             const float* __restrict__ W1, const float* __restrict__ W2,
                             __nv_bfloat16* __restrict__ wh, __nv_bfloat16* __restrict__ wl) {
    size_t j4 = ((size_t)blockIdx.x*256 + threadIdx.x) * 4;
    if (j4 >= 18ull*262144) return;
    size_t uu = j4 >> 18;
    int u = (int)(uu % 6), i = (int)(uu / 6);
    size_t off = j4 & 262143;
    const float* src;
    switch (u) { case 0: src=Wq; break; case 1: src=Wk; break; case 2: src=Wv; break;
                 case 3: src=Wo; break; case 4: src=W1; break; default: src=W2; }
    float4 f = *(const float4*)(src + (size_t)i*262144 + off);
    cvst(f.x, f.y, wh+j4,   wl+j4);
    cvst(f.z, f.w, wh+j4+2, wl+j4+2);
}

// ---------------- embedding -------------------------------------------------
__global__ void embed_kernel(const float* __restrict__ x,
                             const float* __restrict__ ck,
                             float* __restrict__ h,
                             __nv_bfloat16* __restrict__ hh,
                             __nv_bfloat16* __restrict__ hl) {
    int bt = blockIdx.x;
    int b = bt >> 9, t = bt & (WIN-1);
    __shared__ float xs[3*CIN];
    int tid = threadIdx.x;
    if (tid < 3*CIN) {
        int w = tid / CIN, c = tid % CIN;
        int src = (t + w - 1 + WIN) & (WIN-1);
        xs[tid] = x[((size_t)b*WIN + src)*CIN + c];
    }
    __syncthreads();
    int d = tid;
    int i2 = (d >> 1) * 2;
    float ang = (float)t * __expf(-(float)i2 * (9.210340371976184f/512.0f));
    float acc = (d & 1) ? cosf(ang) : sinf(ang);
#pragma unroll 1
    for (int wc = 0; wc < 3*CIN; wc++)
        acc += xs[wc] * ck[(size_t)wc*DM + d];
    size_t idx = (size_t)bt*DM + d;
    h[idx] = acc;
    cvst1(acc, hh + idx, hl + idx);
}

// ---------------- dense GEMM: 64x128 tile, 2-stage cp.async, 3 CTAs/SM ------
struct GemmJob {
    const __nv_bfloat16* Wh; const __nv_bfloat16* Wl;
    const float* bias;
    float* Cf; __nv_bfloat16* Ch; __nv_bfloat16* Cl;
};

#define AH_OFF 0
#define AL_OFF 2560
#define BH_OFF 5120
#define BL_OFF 9472
#define BUF_SZ 13824
#define MG_SMEM (2*BUF_SZ*2)

__device__ __forceinline__ void mg_issue(uint32_t smb, int buf, int tid,
        const __nv_bfloat16* Ah, const __nv_bfloat16* Al,
        const __nv_bfloat16* Wh, const __nv_bfloat16* Wl, int kt) {
    int ar = tid >> 2, ac = (tid & 3) * 8;
    int br = tid >> 3, bc = (tid & 7) * 16;
    uint32_t base = smb + (uint32_t)buf * (BUF_SZ*2);
    const __nv_bfloat16* ga  = Ah + (size_t)ar*512 + kt*32 + ac;
    const __nv_bfloat16* gal = Al + (size_t)ar*512 + kt*32 + ac;
    cpa16(base + (uint32_t)(AH_OFF + ar*40 + ac)*2, ga);
    cpa16(base + (uint32_t)(AL_OFF + ar*40 + ac)*2, gal);
    const __nv_bfloat16* gb  = Wh + (size_t)(kt*32 + br)*512 + bc;
    const __nv_bfloat16* gbl = Wl + (size_t)(kt*32 + br)*512 + bc;
    uint32_t sb  = base + (uint32_t)(BH_OFF + br*136 + bc)*2;
    uint32_t sbl = base + (uint32_t)(BL_OFF + br*136 + bc)*2;
    cpa16(sb, gb);        cpa16(sb+16, gb+8);
    cpa16(sbl, gbl);      cpa16(sbl+16, gbl+8);
    asm volatile("cp.async.commit_group;\n");
}

__device__ __forceinline__ void mg_compute(uint32_t smb, int buf, int tid,
                                           float (*acc)[4][4]) {
    int l = tid & 31, w = tid >> 5, wm = w & 1, wn = w >> 1;
    int lr = l & 15, lc8 = (l >> 4) << 3;
    uint32_t base = smb + (uint32_t)buf * (BUF_SZ*2);
#pragma unroll
    for (int ks = 0; ks < 32; ks += 16) {
        uint32_t ah[2][4], al[2][4];
#pragma unroll
        for (int fm = 0; fm < 2; fm++) {
            uint32_t aoff = (uint32_t)((wm*32 + fm*16 + lr)*40 + ks + lc8) * 2;
            ldsm4(base + AH_OFF*2 + aoff, ah[fm][0], ah[fm][1], ah[fm][2], ah[fm][3]);
            ldsm4(base + AL_OFF*2 + aoff, al[fm][0], al[fm][1], al[fm][2], al[fm][3]);
        }
#pragma unroll
        for (int fnp = 0; fnp < 2; fnp++) {
            uint32_t boff = (uint32_t)((ks + lr)*136 + wn*32 + fnp*16 + lc8) * 2;
            uint32_t bh[4], bl[4];
            ldsm4t(base + BH_OFF*2 + boff, bh[0], bh[1], bh[2], bh[3]);
            ldsm4t(base + BL_OFF*2 + boff, bl[0], bl[1], bl[2], bl[3]);
#pragma unroll
            for (int fm = 0; fm < 2; fm++) {
                mmabf(acc[fm][fnp*2],   ah[fm], bh[0], bh[1]);
                mmabf(acc[fm][fnp*2],   ah[fm], bl[0], bl[1]);
                mmabf(acc[fm][fnp*2],   al[fm], bh[0], bh[1]);
                mmabf(acc[fm][fnp*2+1], ah[fm], bh[2], bh[3]);
                mmabf(acc[fm][fnp*2+1], ah[fm], bl[2], bl[3]);
                mmabf(acc[fm][fnp*2+1], al[fm], bh[2], bh[3]);
            }
        }
    }
}

template<bool GELU>
__global__ __launch_bounds__(256, 3)
void mgemm(const __nv_bfloat16* __restrict__ Ah, const __nv_bfloat16* __restrict__ Al,
           GemmJob j0, GemmJob j1, GemmJob j2) {
    extern __shared__ __nv_bfloat16 sm[];
    GemmJob jb = (blockIdx.z == 0) ? j0 : ((blockIdx.z == 1) ? j1 : j2);
    int tid = threadIdx.x;
    const __nv_bfloat16* Abh = Ah + (size_t)blockIdx.x * 64 * 512;
    const __nv_bfloat16* Abl = Al + (size_t)blockIdx.x * 64 * 512;
    const __nv_bfloat16* Wbh = jb.Wh + blockIdx.y * 128;
    const __nv_bfloat16* Wbl = jb.Wl + blockIdx.y * 128;
    uint32_t smb = smaddr(sm);

    mg_issue(smb, 0, tid, Abh, Abl, Wbh, Wbl, 0);
    mg_issue(smb, 1, tid, Abh, Abl, Wbh, Wbl, 1);

    float acc[2][4][4] = {};
    for (int kt = 0; kt < 16; kt++) {
        int buf = kt & 1;
        if (kt < 15) asm volatile("cp.async.wait_group 1;\n");
        else         asm volatile("cp.async.wait_group 0;\n");
        __syncthreads();
        mg_compute(smb, buf, tid, acc);
        if (kt < 14) {
            __syncthreads();
            mg_issue(smb, buf, tid, Abh, Abl, Wbh, Wbl, kt+2);
        }
    }

    int l = tid & 31, w = tid >> 5, wm = w & 1, wn = w >> 1;
    int g = l >> 2, t2 = (l & 3) * 2;
    int rowb = blockIdx.x*64 + wm*32;
    int colb = blockIdx.y*128 + wn*32;
#pragma unroll
    for (int fm = 0; fm < 2; fm++) {
#pragma unroll
        for (int fn = 0; fn < 4; fn++) {
            int col = colb + fn*8 + t2;
            float bx0 = jb.bias[col], bx1 = jb.bias[col+1];
            float o0 = acc[fm][fn][0] + bx0, o1 = acc[fm][fn][1] + bx1;
            float o2 = acc[fm][fn][2] + bx0, o3 = acc[fm][fn][3] + bx1;
            if (GELU) {
                o0 = 0.5f*o0*(1.0f + erff(o0*0.70710678118654752f));
                o1 = 0.5f*o1*(1.0f + erff(o1*0.70710678118654752f));
                o2 = 0.5f*o2*(1.0f + erff(o2*0.70710678118654752f));
                o3 = 0.5f*o3*(1.0f + erff(o3*0.70710678118654752f));
            }
            int r0 = rowb + fm*16 + g;
            if (jb.Cf) {
                float2 p0 = {o0, o1}, p1 = {o2, o3};
                *(float2*)(jb.Cf + (size_t)r0*512 + col)     = p0;
                *(float2*)(jb.Cf + (size_t)(r0+8)*512 + col) = p1;
            }
            if (jb.Ch) {
                cvst(o0, o1, jb.Ch + (size_t)r0*512 + col,     jb.Cl + (size_t)r0*512 + col);
                cvst(o2, o3, jb.Ch + (size_t)(r0+8)*512 + col, jb.Cl + (size_t)(r0+8)*512 + col);
            }
        }
    }
}

// ---------------- fused scores + softmax + S@V ------------------------------
#define FQH 0
#define FQL 4608
#define FKH 9216
#define FKL 46080
#define FVH 0
#define FVL 4608
#define FSH 9216
#define FSL 42496
#define FS_SMEM 165888

__global__ __launch_bounds__(512)
void fscores(const __nv_bfloat16* __restrict__ qh, const __nv_bfloat16* __restrict__ ql,
             const __nv_bfloat16* __restrict__ kh, const __nv_bfloat16* __restrict__ kl,
             const __nv_bfloat16* __restrict__ vh, const __nv_bfloat16* __restrict__ vl,
             float* __restrict__ out,
             __nv_bfloat16* __restrict__ t1h, __nv_bfloat16* __restrict__ t1l) {
    extern __shared__ __nv_bfloat16 sm[];
    __shared__ float red[64][8];
    int tid = threadIdx.x;
    int bh = blockIdx.y, b = bh >> 3, hhd = bh & 7;
    int l0 = blockIdx.x * 64;

    {
        int r = tid >> 3, c = (tid & 7) * 8;
        size_t qoff = ((size_t)(b*512 + l0 + r))*512 + hhd*64 + c;
        int qi = r*72 + c;
        *(uint4*)&sm[FQH + qi] = *(const uint4*)(qh + qoff);
        *(uint4*)&sm[FQL + qi] = *(const uint4*)(ql + qoff);
#pragma unroll
        for (int i = 0; i < 8; i++) {
            int kr = r + i*64;
            size_t koff = ((size_t)(b*512 + kr))*512 + hhd*64 + c;
            int ki = kr*72 + c;
            *(uint4*)&sm[FKH + ki] = *(const uint4*)(kh + koff);
            *(uint4*)&sm[FKL + ki] = *(const uint4*)(kl + koff);
        }
    }
    __syncthreads();

    uint32_t smb = smaddr(sm);
    int l = tid & 31, w = tid >> 5;
    int wn = w & 7, wm = w >> 3;
    int lr = l & 15, lc8 = (l >> 4) << 3;
    float acc[2][8][4] = {};
#pragma unroll
    for (int ks = 0; ks < 64; ks += 16) {
        uint32_t ah[2][4], al[2][4];
#pragma unroll
        for (int fm = 0; fm < 2; fm++) {
            uint32_t aoff = (uint32_t)((wm*32 + fm*16 + lr)*72 + ks + lc8) * 2;
            ldsm4(smb + FQH*2 + aoff, ah[fm][0], ah[fm][1], ah[fm][2], ah[fm][3]);
            ldsm4(smb + FQL*2 + aoff, al[fm][0], al[fm][1], al[fm][2], al[fm][3]);
        }
#pragma unroll
        for (int fnp = 0; fnp < 4; fnp++) {
            uint32_t boff = (uint32_t)((wn*64 + fnp*16 + lr)*72 + ks + lc8) * 2;
            uint32_t khr[4], klr[4];
            ldsm4(smb + FKH*2 + boff, khr[0], khr[1], khr[2], khr[3]);
            ldsm4(smb + FKL*2 + boff, klr[0], klr[1], klr[2], klr[3]);
#pragma unroll
            for (int fm = 0; fm < 2; fm++) {
                mmabf(acc[fm][fnp*2],   ah[fm], khr[0], khr[2]);
                mmabf(acc[fm][fnp*2],   ah[fm], klr[0], klr[2]);
                mmabf(acc[fm][fnp*2],   al[fm], khr[0], khr[2]);
                mmabf(acc[fm][fnp*2+1], ah[fm], khr[1], khr[3]);
                mmabf(acc[fm][fnp*2+1], ah[fm], klr[1], klr[3]);
                mmabf(acc[fm][fnp*2+1], al[fm], khr[1], khr[3]);
            }
        }
    }

#pragma unroll
    for (int fm = 0; fm < 2; fm++)
#pragma unroll
        for (int fn = 0; fn < 8; fn++)
#pragma unroll
            for (int e = 0; e < 4; e++) acc[fm][fn][e] *= 0.125f;

    int g = l >> 2, t2 = (l & 3) * 2;
    float tmax[2][2] = {{-1e30f,-1e30f},{-1e30f,-1e30f}};
#pragma unroll
    for (int fm = 0; fm < 2; fm++)
#pragma unroll
        for (int fn = 0; fn < 8; fn++) {
            tmax[fm][0] = fmaxf(tmax[fm][0], fmaxf(acc[fm][fn][0], acc[fm][fn][1]));
            tmax[fm][1] = fmaxf(tmax[fm][1], fmaxf(acc[fm][fn][2], acc[fm][fn][3]));
        }
#pragma unroll
    for (int o = 1; o <= 2; o <<= 1) {
#pragma unroll
        for (int fm = 0; fm < 2; fm++) {
            tmax[fm][0] = fmaxf(tmax[fm][0], __shfl_xor_sync(0xffffffff, tmax[fm][0], o));
            tmax[fm][1] = fmaxf(tmax[fm][1], __shfl_xor_sync(0xffffffff, tmax[fm][1], o));
        }
    }
    if ((l & 3) == 0) {
#pragma unroll
        for (int fm = 0; fm < 2; fm++) {
            red[wm*32 + fm*16 + g][wn]     = tmax[fm][0];
            red[wm*32 + fm*16 + g + 8][wn] = tmax[fm][1];
        }
    }
    __syncthreads();
    float rmax[2][2];
#pragma unroll
    for (int fm = 0; fm < 2; fm++)
#pragma unroll
        for (int hf = 0; hf < 2; hf++) {
            int r = wm*32 + fm*16 + g + hf*8;
            float m = red[r][0];
#pragma unroll
            for (int ww = 1; ww < 8; ww++) m = fmaxf(m, red[r][ww]);
            rmax[fm][hf] = m;
        }
    __syncthreads();

    float tsum[2][2] = {};
#pragma unroll
    for (int fm = 0; fm < 2; fm++)
#pragma unroll
        for (int fn = 0; fn < 8; fn++) {
            acc[fm][fn][0] = __expf(acc[fm][fn][0] - rmax[fm][0]);
            acc[fm][fn][1] = __expf(acc[fm][fn][1] - rmax[fm][0]);
            acc[fm][fn][2] = __expf(acc[fm][fn][2] - rmax[fm][1]);
            acc[fm][fn][3] = __expf(acc[fm][fn][3] - rmax[fm][1]);
            tsum[fm][0] += acc[fm][fn][0] + acc[fm][fn][1];
            tsum[fm][1] += acc[fm][fn][2] + acc[fm][fn][3];
        }
#pragma unroll
    for (int o = 1; o <= 2; o <<= 1) {
#pragma unroll
        for (int fm = 0; fm < 2; fm++) {
            tsum[fm][0] += __shfl_xor_sync(0xffffffff, tsum[fm][0], o);
            tsum[fm][1] += __shfl_xor_sync(0xffffffff, tsum[fm][1], o);
        }
    }
    if ((l & 3) == 0) {
#pragma unroll
        for (int fm = 0; fm < 2; fm++) {
            red[wm*32 + fm*16 + g][wn]     = tsum[fm][0];
            red[wm*32 + fm*16 + g + 8][wn] = tsum[fm][1];
        }
    }
    __syncthreads();
    float rinv[2][2];
#pragma unroll
    for (int fm = 0; fm < 2; fm++)
#pragma unroll
        for (int hf = 0; hf < 2; hf++) {
            int r = wm*32 + fm*16 + g + hf*8;
            float s = red[r][0];
#pragma unroll
            for (int ww = 1; ww < 8; ww++) s += red[r][ww];
            rinv[fm][hf] = 1.0f / s;
        }

    float* ob = out + ((size_t)bh*512 + l0)*512;
#pragma unroll
    for (int fm = 0; fm < 2; fm++)
#pragma unroll
        for (int fn = 0; fn < 8; fn++) {
            int row0 = wm*32 + fm*16 + g;
            int col = wn*64 + fn*8 + t2;
            float s0 = acc[fm][fn][0]*rinv[fm][0], s1 = acc[fm][fn][1]*rinv[fm][0];
            float s2 = acc[fm][fn][2]*rinv[fm][1], s3 = acc[fm][fn][3]*rinv[fm][1];
            float2 p0 = {s0, s1}, p1 = {s2, s3};
            *(float2*)(ob + (size_t)row0*512 + col)     = p0;
            *(float2*)(ob + (size_t)(row0+8)*512 + col) = p1;
            cvst(s0, s1, &sm[FSH + row0*520 + col],     &sm[FSL + row0*520 + col]);
            cvst(s2, s3, &sm[FSH + (row0+8)*520 + col], &sm[FSL + (row0+8)*520 + col]);
        }
    __syncthreads();

    float acc2[2][4] = {};
    for (int kc = 0; kc < 8; kc++) {
        {
            int r = tid >> 3, c = (tid & 7) * 8;
            size_t voff = ((size_t)(b*512 + kc*64 + r))*512 + hhd*64 + c;
            *(uint4*)&sm[FVH + r*72 + c] = *(const uint4*)(vh + voff);
            *(uint4*)&sm[FVL + r*72 + c] = *(const uint4*)(vl + voff);
        }
        __syncthreads();
#pragma unroll
        for (int ks = 0; ks < 64; ks += 16) {
            uint32_t sa[2][4], sl2[2][4];
#pragma unroll
            for (int fm = 0; fm < 2; fm++) {
                uint32_t aoff = (uint32_t)((wm*32 + fm*16 + lr)*520 + kc*64 + ks + lc8) * 2;
                ldsm4(smb + FSH*2 + aoff, sa[fm][0], sa[fm][1], sa[fm][2], sa[fm][3]);
                ldsm4(smb + FSL*2 + aoff, sl2[fm][0], sl2[fm][1], sl2[fm][2], sl2[fm][3]);
            }
            uint32_t boff = (uint32_t)((ks + lr)*72 + wn*8) * 2;
            uint32_t bh2[2], bl2[2];
            ldsm2t(smb + FVH*2 + boff, bh2[0], bh2[1]);
            ldsm2t(smb + FVL*2 + boff, bl2[0], bl2[1]);
#pragma unroll
            for (int fm = 0; fm < 2; fm++) {
                mmabf(acc2[fm], sa[fm],  bh2[0], bh2[1]);
                mmabf(acc2[fm], sa[fm],  bl2[0], bl2[1]);
                mmabf(acc2[fm], sl2[fm], bh2[0], bh2[1]);
            }
        }
        if (kc < 7) __syncthreads();
    }

#pragma unroll
    for (int fm = 0; fm < 2; fm++) {
        int row0 = wm*32 + fm*16 + g;
        int col = wn*8 + t2;
        size_t p0 = ((size_t)(b*512 + l0 + row0))*512 + hhd*64 + col;
        size_t p1 = ((size_t)(b*512 + l0 + row0 + 8))*512 + hhd*64 + col;
        cvst(acc2[fm][0], acc2[fm][1], t1h + p0, t1l + p0);
        cvst(acc2[fm][2], acc2[fm][3], t1h + p1, t1l + p1);
    }
}

// ---------------- sigma projection ------------------------------------------
__global__ __launch_bounds__(128)
void sig4_kernel(const float* __restrict__ h, const float* __restrict__ Ws,
                 const float* __restrict__ bs, float* __restrict__ sig) {
    int warp = threadIdx.x >> 5, lane = threadIdx.x & 31;
    int row = blockIdx.x*4 + warp;
    const float* hr = h + (size_t)row*512;
    float s[8] = {};
#pragma unroll
    for (int i = 0; i < 16; i++) {
        int k = i*32 + lane;
        float hv = hr[k];
        float4 wa = *(const float4*)(Ws + k*8);
        float4 wb = *(const float4*)(Ws + k*8 + 4);
        s[0] += hv*wa.x; s[1] += hv*wa.y; s[2] += hv*wa.z; s[3] += hv*wa.w;
        s[4] += hv*wb.x; s[5] += hv*wb.y; s[6] += hv*wb.z; s[7] += hv*wb.w;
    }
#pragma unroll
    for (int off = 16; off > 0; off >>= 1)
#pragma unroll
        for (int o = 0; o < 8; o++) s[o] += __shfl_xor_sync(0xffffffff, s[o], off);
    if (lane < 8) sig[row*8 + lane] = s[lane] + bs[lane];
}

// ---------------- prior + sigma ---------------------------------------------
__global__ __launch_bounds__(128)
void prior_kernel(const float* __restrict__ sig,
                  float* __restrict__ prior, float* __restrict__ sigma) {
    int idx = blockIdx.x;
    int l = idx & (WIN-1);
    int bh = idx >> 9;
    int b = bh >> 3, hh = bh & 7;
    float sv = sig[((size_t)b*WIN + l)*NH + hh];
    float sgm = 1.0f/(1.0f + __expf(-5.0f*sv)) + 1e-5f;
    float sg  = __expf(sgm * 1.0986122886681098f) - 1.0f;
    float inv = 0.3989422804014327f / sg;
    float cc  = -1.0f/(2.0f*sg*sg);
    size_t base = ((size_t)bh*WIN + l)*WIN;
    int s0 = threadIdx.x * 4;
    float d0 = (float)(l - s0), d1 = d0 - 1.0f, d2 = d0 - 2.0f, d3 = d0 - 3.0f;
    float4 pr;
    pr.x = inv*__expf(cc*d0*d0); pr.y = inv*__expf(cc*d1*d1);
    pr.z = inv*__expf(cc*d2*d2); pr.w = inv*__expf(cc*d3*d3);
    *(float4*)(prior + base + s0) = pr;
    float4 sgv = {sg, sg, sg, sg};
    *(float4*)(sigma + base + s0) = sgv;
}

// ---------------- LayerNorm (warp-shuffle reductions) ------------------------
__global__ void ln_kernel(const float* __restrict__ x, const float* __restrict__ res,
                          const float* __restrict__ g, const float* __restrict__ bb,
                          float* __restrict__ outf,
                          __nv_bfloat16* __restrict__ outh, __nv_bfloat16* __restrict__ outl) {
    __shared__ float ws[8];
    size_t row = blockIdx.x;
    int tid = threadIdx.x;
    const float* xr = x + row*DM;
    float v0 = xr[tid], v1 = xr[tid+256];
    if (res) { const float* rr = res + row*DM; v0 += rr[tid]; v1 += rr[tid+256]; }
    float mu = blocksum256(v0 + v1, ws, tid) * (1.0f/DM);
    float d0 = v0 - mu, d1 = v1 - mu;
    float var = blocksum256(d0*d0 + d1*d1, ws, tid) * (1.0f/DM);
    float r = rsqrtf(var + 1e-3f);
    float y0 = d0*r*g[tid]     + bb[tid];
    float y1 = d1*r*g[tid+256] + bb[tid+256];
    size_t i0 = row*DM + tid, i1 = i0 + 256;
    outf[i0] = y0;
    outf[i1] = y1;
    if (outh) {
        cvst1(y0, outh + i0, outl + i0);
        cvst1(y1, outh + i1, outl + i1);
    }
}

// ---------------- fused final LayerNorm + projection -------------------------
__global__ void lnproj_kernel(const float* __restrict__ x,
                              const float* __restrict__ g, const float* __restrict__ bb,
                              const float* __restrict__ Wp, const float* __restrict__ bp,
                              float* __restrict__ out) {
    __shared__ float hs[512];
    __shared__ float ws[8];
    size_t row = blockIdx.x;
    int tid = threadIdx.x;
    const float* xr = x + row*DM;
    float v0 = xr[tid], v1 = xr[tid+256];
    float mu = blocksum256(v0 + v1, ws, tid) * (1.0f/DM);
    float d0 = v0 - mu, d1 = v1 - mu;
    float var = blocksum256(d0*d0 + d1*d1, ws, tid) * (1.0f/DM);
    float r = rsqrtf(var + 1e-3f);
    hs[tid]     = d0*r*g[tid]     + bb[tid];
    hs[tid+256] = d1*r*g[tid+256] + bb[tid+256];
    __syncthreads();
    int warp = tid >> 5, lane = tid & 31;
    for (int c = warp; c < COUT; c += 8) {
        float sum = 0.f;
#pragma unroll
        for (int k2 = lane; k2 < 512; k2 += 32) sum += hs[k2] * Wp[(size_t)k2*COUT + c];
#pragma unroll
        for (int o = 16; o > 0; o >>= 1) sum += __shfl_xor_sync(0xffffffff, sum, o);
        if (lane == 0) out[row*COUT + c] = sum + bp[c];
    }
}

// ---------------- host orchestration ----------------------------------------
extern "C" void kernel_launch(void* const* d_in, const int* in_sizes, int n_in,
                              void* d_out, int out_size) {
    const float* x    = (const float*)d_in[0];
    const float* ck   = (const float*)d_in[1];
    const float* Wq   = (const float*)d_in[2];
    const float* bq   = (const float*)d_in[3];
    const float* Wk   = (const float*)d_in[4];
    const float* bk   = (const float*)d_in[5];
    const float* Wv   = (const float*)d_in[6];
    const float* bv   = (const float*)d_in[7];
    const float* Ws   = (const float*)d_in[8];
    const float* bs   = (const float*)d_in[9];
    const float* Wo   = (const float*)d_in[10];
    const float* bo   = (const float*)d_in[11];
    const float* W1   = (const float*)d_in[12];
    const float* b1   = (const float*)d_in[13];
    const float* W2   = (const float*)d_in[14];
    const float* b2   = (const float*)d_in[15];
    const float* ln1g = (const float*)d_in[16];
    const float* ln1b = (const float*)d_in[17];
    const float* ln2g = (const float*)d_in[18];
    const float* ln2b = (const float*)d_in[19];
    const float* lnfg = (const float*)d_in[20];
    const float* lnfb = (const float*)d_in[21];
    const float* Wp   = (const float*)d_in[22];
    const float* bp   = (const float*)d_in[23];
    float* out = (float*)d_out;

    float *h, *t2, *sg;
    __nv_bfloat16 *hh, *hl, *qh, *ql, *kh, *kl, *vh, *vl, *t1h, *t1l, *wh, *wl;
    cudaGetSymbolAddress((void**)&h,   g_h);
    cudaGetSymbolAddress((void**)&t2,  g_t2);
    cudaGetSymbolAddress((void**)&sg,  g_sig);
    cudaGetSymbolAddress((void**)&hh,  g_hh);
    cudaGetSymbolAddress((void**)&hl,  g_hl);
    cudaGetSymbolAddress((void**)&qh,  g_qh);
    cudaGetSymbolAddress((void**)&ql,  g_ql);
    cudaGetSymbolAddress((void**)&kh,  g_kh);
    cudaGetSymbolAddress((void**)&kl,  g_kl);
    cudaGetSymbolAddress((void**)&vh,  g_vh);
    cudaGetSymbolAddress((void**)&vl,  g_vl);
    cudaGetSymbolAddress((void**)&t1h, g_t1h);
    cudaGetSymbolAddress((void**)&t1l, g_t1l);
    cudaGetSymbolAddress((void**)&wh,  g_wh);
    cudaGetSymbolAddress((void**)&wl,  g_wl);

    cudaFuncSetAttribute(mgemm<false>, cudaFuncAttributeMaxDynamicSharedMemorySize, MG_SMEM);
    cudaFuncSetAttribute(mgemm<true>,  cudaFuncAttributeMaxDynamicSharedMemorySize, MG_SMEM);
    cudaFuncSetAttribute(fscores,      cudaFuncAttributeMaxDynamicSharedMemorySize, FS_SMEM);

    wconv_kernel<<<4608, 256>>>(Wq, Wk, Wv, Wo, W1, W2, wh, wl);
    embed_kernel<<<ROWS, DM>>>(x, ck, h, hh, hl);

    dim3 g1(64, 4, 1);
    dim3 g3(64, 4, 3);
    for (int i = 0; i < NL; i++) {
        size_t wbase = (size_t)i*6*262144;
        GemmJob jq = { wh + wbase + 0*262144, wl + wbase + 0*262144, bq + i*DM, nullptr, qh, ql };
        GemmJob jk = { wh + wbase + 1*262144, wl + wbase + 1*262144, bk + i*DM, nullptr, kh, kl };
        GemmJob jv = { wh + wbase + 2*262144, wl + wbase + 2*262144, bv + i*DM, nullptr, vh, vl };
        GemmJob jo = { wh + wbase + 3*262144, wl + wbase + 3*262144, bo + i*DM, t2, nullptr, nullptr };
        GemmJob jf1 = { wh + wbase + 4*262144, wl + wbase + 4*262144, b1 + i*DM, nullptr, t1h, t1l };
        GemmJob jf2 = { wh + wbase + 5*262144, wl + wbase + 5*262144, b2 + i*DM, t2, nullptr, nullptr };

        mgemm<false><<<g3, 256, MG_SMEM>>>(hh, hl, jq, jk, jv);
        sig4_kernel<<<ROWS/4, 128>>>(h, Ws + (size_t)i*DM*NH, bs + i*NH, sg);

        float* ser = out + SERIES_OFF + (size_t)i*LAYER_ELEMS;
        fscores<<<dim3(8, 64), 512, FS_SMEM>>>(qh, ql, kh, kl, vh, vl, ser, t1h, t1l);
        prior_kernel<<<BATCH*NH*WIN, 128>>>(sg,
                out + PRIOR_OFF + (size_t)i*LAYER_ELEMS,
                out + SIGMA_OFF + (size_t)i*LAYER_ELEMS);

        mgemm<false><<<g1, 256, MG_SMEM>>>(t1h, t1l, jo, jo, jo);
        ln_kernel<<<ROWS, 256>>>(h, t2, ln1g + i*DM, ln1b + i*DM, h, hh, hl);

        mgemm<true ><<<g1, 256, MG_SMEM>>>(hh, hl, jf1, jf1, jf1);
        mgemm<false><<<g1, 256, MG_SMEM>>>(t1h, t1l, jf2, jf2, jf2);
        ln_kernel<<<ROWS, 256>>>(h, t2, ln2g + i*DM, ln2b + i*DM, h, hh, hl);
    }

    lnproj_kernel<<<ROWS, 256>>>(h, lnfg, lnfb, Wp, bp, out);
}